// round 11
// baseline (speedup 1.0000x reference)
#include <cuda_runtime.h>
#include <cuda_bf16.h>
#include <cstdint>

#define NN 50000
#define EE 800000
#define DD 128
#define GRIDP 148
#define NT64 782             // ceil(50000/64)

// ---------------- scratch (static device globals) ----------------
__device__ float g_y0[(size_t)NN * DD];
__device__ int8_t g_A1[(size_t)NN * 128];
__device__ int8_t g_A0[(size_t)NN * 128];
__device__ float  g_sA[NN];
__device__ int8_t g_H1[(size_t)NN * 256];
__device__ int8_t g_H0[(size_t)NN * 256];
__device__ float  g_sH[NN];
__device__ int8_t g_WB1[4 * 32768];
__device__ int8_t g_WB0[4 * 32768];
__device__ float  g_sW[768];     // [0:256)=W1_0, [256:384)=W2_0, [384:640)=W1_1, [640:768)=W2_1
__device__ int g_cnt[NN];
__device__ uint32_t g_payload[(size_t)NN * 64];

// ---------------- PTX helpers ----------------
__device__ __forceinline__ uint32_t smem_u32(const void* p) {
    uint32_t a;
    asm("{ .reg .u64 t; cvta.to.shared.u64 t, %1; cvt.u32.u64 %0, t; }" : "=r"(a) : "l"(p));
    return a;
}
__device__ __forceinline__ void cp_async16(uint32_t dst, const void* src, int srcbytes) {
    asm volatile("cp.async.cg.shared.global [%0], [%1], 16, %2;"
                 :: "r"(dst), "l"(src), "r"(srcbytes) : "memory");
}
__device__ __forceinline__ void cp_commit() { asm volatile("cp.async.commit_group;" ::: "memory"); }
__device__ __forceinline__ void cp_wait0()  { asm volatile("cp.async.wait_group 0;" ::: "memory"); }

__device__ __forceinline__ void ldsm_x4(uint32_t& r0, uint32_t& r1, uint32_t& r2, uint32_t& r3,
                                        uint32_t addr) {
    asm volatile("ldmatrix.sync.aligned.m8n8.x4.shared.b16 {%0,%1,%2,%3}, [%4];"
                 : "=r"(r0), "=r"(r1), "=r"(r2), "=r"(r3) : "r"(addr));
}
__device__ __forceinline__ void imma16832(int* d, const uint32_t* a, const uint32_t* b) {
    asm volatile(
        "mma.sync.aligned.m16n8k32.row.col.s32.s8.s8.s32 "
        "{%0,%1,%2,%3}, {%4,%5,%6,%7}, {%8,%9}, {%0,%1,%2,%3};"
        : "+r"(d[0]), "+r"(d[1]), "+r"(d[2]), "+r"(d[3])
        : "r"(a[0]), "r"(a[1]), "r"(a[2]), "r"(a[3]), "r"(b[0]), "r"(b[1]));
}
__device__ __forceinline__ uint32_t pack4(int b0, int b1, int b2, int b3) {
    return (uint32_t)(b0 & 255) | ((uint32_t)(b1 & 255) << 8) |
           ((uint32_t)(b2 & 255) << 16) | ((uint32_t)(b3 & 255) << 24);
}
__device__ __forceinline__ void split16(int q, int& h, int& l) {
    h = (q + 128) >> 8;
    l = q - (h << 8);
}
__device__ __forceinline__ float warp_max(float m) {
#pragma unroll
    for (int o = 16; o > 0; o >>= 1) m = fmaxf(m, __shfl_xor_sync(0xFFFFFFFFu, m, o));
    return m;
}

// ---------------- prep: weight quantization (per-output-col) + zero cnt -----
__global__ void __launch_bounds__(256)
prep_kernel(const float* __restrict__ W10, const float* __restrict__ W20,
            const float* __restrict__ W11, const float* __restrict__ W21,
            int8_t* __restrict__ WB1, int8_t* __restrict__ WB0,
            float* __restrict__ sW, int* __restrict__ cnt) {
    int b = blockIdx.x;
    if (b >= 96) {
        int i = (b - 96) * 256 + threadIdx.x;
        if (i < NN) cnt[i] = 0;
        return;
    }
    int g = b * 8 + (threadIdx.x >> 5);   // warp id 0..767
    int lane = threadIdx.x & 31;
    const float* W; int K, N, n; size_t ob; int so;
    if (g < 256)      { W = W10; K = 128; N = 256; n = g;       ob = 0;     so = 0;   }
    else if (g < 384) { W = W20; K = 256; N = 128; n = g - 256; ob = 32768; so = 256; }
    else if (g < 640) { W = W11; K = 128; N = 256; n = g - 384; ob = 65536; so = 384; }
    else              { W = W21; K = 256; N = 128; n = g - 640; ob = 98304; so = 640; }
    int nj = K >> 5;  // 4 or 8
    float v[8];
    float m = 0.f;
    for (int j = 0; j < nj; j++) {
        v[j] = W[(size_t)(lane + j * 32) * N + n];
        m = fmaxf(m, fabsf(v[j]));
    }
    m = warp_max(m);
    float s_inv = (m > 1e-30f) ? 32512.f / m : 0.f;
    for (int j = 0; j < nj; j++) {
        int q = __float2int_rn(v[j] * s_inv);
        int h, l;
        split16(q, h, l);
        WB1[ob + (size_t)n * K + lane + j * 32] = (int8_t)h;
        WB0[ob + (size_t)n * K + lane + j * 32] = (int8_t)l;
    }
    if (lane == 0) sW[so + n] = m * (1.f / 32512.f);
}

// ---------------- bucket fill ----------------
__global__ void __launch_bounds__(256)
fill_kernel(const int* __restrict__ ei, const int* __restrict__ ea,
            int* __restrict__ cnt, uint32_t* __restrict__ payload, int E) {
    int e = blockIdx.x * 256 + threadIdx.x;
    if (e >= E) return;
    int src = ei[e];
    int dst = ei[E + e];
    int a0 = ea[2 * e];
    int a1 = ea[2 * e + 1];
    int pos = atomicAdd(&cnt[dst], 1);
    payload[((size_t)dst << 6) + pos] = (uint32_t)src | ((uint32_t)(a0 * 3 + a1) << 16);
}

// ---------------- gather -> int8 digits + per-row scale ----------------
__global__ void __launch_bounds__(256)
gather_kernel(const float* __restrict__ x,
              const int* __restrict__ cnt, const uint32_t* __restrict__ payload,
              const float* __restrict__ ee1, const float* __restrict__ ee2,
              int8_t* __restrict__ A1, int8_t* __restrict__ A0,
              float* __restrict__ sA, int N) {
    __shared__ float combo[18 * 128];
    const int tid = threadIdx.x;
#pragma unroll
    for (int k = 0; k < 9; k++) {
        int idx = tid + k * 256;
        int c = idx >> 7, d = idx & 127;
        combo[idx] = ee1[(c / 3) * 128 + d] + ee2[(c % 3) * 128 + d];
    }
    __syncthreads();

    const int lane = tid & 31;
    const int n = blockIdx.x * 8 + (tid >> 5);
    if (n >= N) return;
    const int d4 = lane * 4;

    const uint32_t* pl = payload + ((size_t)n << 6);
    int deg = cnt[n];
    float4 acc = make_float4(0.f, 0.f, 0.f, 0.f);
    int i = 0;
    for (; i + 3 < deg; i += 4) {
        uint32_t p0 = pl[i], p1 = pl[i + 1], p2 = pl[i + 2], p3 = pl[i + 3];
        float4 x0 = *(const float4*)(x + (size_t)(p0 & 0xFFFF) * 128 + d4);
        float4 x1 = *(const float4*)(x + (size_t)(p1 & 0xFFFF) * 128 + d4);
        float4 x2 = *(const float4*)(x + (size_t)(p2 & 0xFFFF) * 128 + d4);
        float4 x3 = *(const float4*)(x + (size_t)(p3 & 0xFFFF) * 128 + d4);
        float4 c0 = *(const float4*)(combo + (p0 >> 16) * 128 + d4);
        float4 c1 = *(const float4*)(combo + (p1 >> 16) * 128 + d4);
        float4 c2 = *(const float4*)(combo + (p2 >> 16) * 128 + d4);
        float4 c3 = *(const float4*)(combo + (p3 >> 16) * 128 + d4);
        acc.x += (x0.x + c0.x) + (x1.x + c1.x) + (x2.x + c2.x) + (x3.x + c3.x);
        acc.y += (x0.y + c0.y) + (x1.y + c1.y) + (x2.y + c2.y) + (x3.y + c3.y);
        acc.z += (x0.z + c0.z) + (x1.z + c1.z) + (x2.z + c2.z) + (x3.z + c3.z);
        acc.w += (x0.w + c0.w) + (x1.w + c1.w) + (x2.w + c2.w) + (x3.w + c3.w);
    }
    for (; i < deg; i++) {
        uint32_t p0 = pl[i];
        float4 x0 = *(const float4*)(x + (size_t)(p0 & 0xFFFF) * 128 + d4);
        float4 c0 = *(const float4*)(combo + (p0 >> 16) * 128 + d4);
        acc.x += x0.x + c0.x;
        acc.y += x0.y + c0.y;
        acc.z += x0.z + c0.z;
        acc.w += x0.w + c0.w;
    }

    float m = fmaxf(fmaxf(fabsf(acc.x), fabsf(acc.y)), fmaxf(fabsf(acc.z), fabsf(acc.w)));
    m = warp_max(m);
    float s_inv = (m > 1e-30f) ? 32512.f / m : 0.f;
    int q0 = __float2int_rn(acc.x * s_inv), q1 = __float2int_rn(acc.y * s_inv);
    int q2 = __float2int_rn(acc.z * s_inv), q3 = __float2int_rn(acc.w * s_inv);
    int h0, l0, h1, l1, h2, l2, h3, l3;
    split16(q0, h0, l0); split16(q1, h1, l1); split16(q2, h2, l2); split16(q3, h3, l3);
    ((uint32_t*)A1)[(size_t)n * 32 + lane] = pack4(h0, h1, h2, h3);
    ((uint32_t*)A0)[(size_t)n * 32 + lane] = pack4(l0, l1, l2, l3);
    if (lane == 0) sA[n] = m * (1.f / 32512.f);
}

// =============== persistent int8 GEMM 1: H = relu(A @ W1^T + b1) ============
// A digits [M,128] i8. W1 digits [256,128] i8 RESIDENT. M-tile 64.
// 8 warps, warp tile 32x64 (wm=(wid&1)*32, wn=(wid>>1)*64).
// Epilogue: fp32 H staged in smem, per-row re-quantized to H1/H0 + sH.
#define I1_SROW 144
#define I1_B (256 * I1_SROW)            // 36864 per digit
#define I1_AB (64 * I1_SROW)            // 9216 per digit
#define I1_ABUF (2 * I1_AB)             // 18432 per buffer
#define I1_HS_OFF (2 * I1_B + 2 * I1_ABUF)   // 110592
#define I1_HROW 1040                    // 260 floats per staged row
#define I1_SMEM (I1_HS_OFF + 64 * I1_HROW)   // 177152

__global__ void __launch_bounds__(256, 1)
gemm1i(const int8_t* __restrict__ A1, const int8_t* __restrict__ A0,
       const float* __restrict__ sA,
       const int8_t* __restrict__ B1, const int8_t* __restrict__ B0,
       const float* __restrict__ sW, const float* __restrict__ bias,
       int8_t* __restrict__ H1, int8_t* __restrict__ H0,
       float* __restrict__ sH, int M) {
    extern __shared__ char smem[];
    const uint32_t sb = smem_u32(smem);
    const uint32_t sB1 = sb;
    const uint32_t sB0 = sb + I1_B;
    const uint32_t sA_0 = sb + 2 * I1_B;

    const int tid  = threadIdx.x;
    const int lane = tid & 31;
    const int wid  = tid >> 5;
    const int wm   = (wid & 1) * 32;
    const int wn   = (wid >> 1) * 64;

    // resident B digits: 256 rows x 128B each
#pragma unroll
    for (int i = 0; i < 8; i++) {
        int id = tid + i * 256;          // 0..2047
        int row = id >> 3, off = (id & 7) * 16;
        uint32_t sdst = (uint32_t)(row * I1_SROW + off);
        cp_async16(sB1 + sdst, B1 + (size_t)row * 128 + off, 16);
        cp_async16(sB0 + sdst, B0 + (size_t)row * 128 + off, 16);
    }

    int t = blockIdx.x;
    if (t < NT64) {
#pragma unroll
        for (int i = 0; i < 2; i++) {
            int id = tid + i * 256;      // 0..511
            int row = id >> 3, off = (id & 7) * 16;
            int grow = t * 64 + row;
            int asz = grow < M ? 16 : 0;
            uint32_t sdst = (uint32_t)(row * I1_SROW + off);
            cp_async16(sA_0 + sdst, A1 + (size_t)grow * 128 + off, asz);
            cp_async16(sA_0 + I1_AB + sdst, A0 + (size_t)grow * 128 + off, asz);
        }
    }
    cp_commit();

    int buf = 0;
    for (; t < NT64; t += GRIDP) {
        cp_wait0();
        __syncthreads();

        int tn = t + GRIDP;
        if (tn < NT64) {
            uint32_t base = sA_0 + (buf ^ 1) * I1_ABUF;
#pragma unroll
            for (int i = 0; i < 2; i++) {
                int id = tid + i * 256;
                int row = id >> 3, off = (id & 7) * 16;
                int grow = tn * 64 + row;
                int asz = grow < M ? 16 : 0;
                uint32_t sdst = (uint32_t)(row * I1_SROW + off);
                cp_async16(base + sdst, A1 + (size_t)grow * 128 + off, asz);
                cp_async16(base + I1_AB + sdst, A0 + (size_t)grow * 128 + off, asz);
            }
        }
        cp_commit();

        const uint32_t cA1 = sA_0 + buf * I1_ABUF;
        const uint32_t cA0 = cA1 + I1_AB;
        int acc1[2][8][4], acc2[2][8][4];
#pragma unroll
        for (int i = 0; i < 2; i++)
#pragma unroll
            for (int j = 0; j < 8; j++)
#pragma unroll
                for (int k = 0; k < 4; k++) { acc1[i][j][k] = 0; acc2[i][j][k] = 0; }

#pragma unroll
        for (int kk = 0; kk < 4; kk++) {         // k-step = 32 int8 = 32B
            const uint32_t kb = (uint32_t)(kk * 32);
            uint32_t a1f[2][4], a0f[2][4];
#pragma unroll
            for (int mt = 0; mt < 2; mt++) {
                uint32_t arow = (uint32_t)(wm + mt * 16 + (lane & 15));
                uint32_t aoff = arow * I1_SROW + kb + ((lane >> 4) << 4);
                ldsm_x4(a1f[mt][0], a1f[mt][1], a1f[mt][2], a1f[mt][3], cA1 + aoff);
                ldsm_x4(a0f[mt][0], a0f[mt][1], a0f[mt][2], a0f[mt][3], cA0 + aoff);
            }
            uint32_t b1f[8][2], b0f[8][2];
#pragma unroll
            for (int np = 0; np < 4; np++) {
                int g = lane >> 3, r = lane & 7;
                uint32_t browi = (uint32_t)(wn + np * 16 + ((g & 2) ? 8 : 0) + r);
                uint32_t boff = browi * I1_SROW + kb + ((g & 1) << 4);
                uint32_t r0, r1, r2, r3;
                ldsm_x4(r0, r1, r2, r3, sB1 + boff);
                b1f[np * 2][0] = r0; b1f[np * 2][1] = r1;
                b1f[np * 2 + 1][0] = r2; b1f[np * 2 + 1][1] = r3;
                ldsm_x4(r0, r1, r2, r3, sB0 + boff);
                b0f[np * 2][0] = r0; b0f[np * 2][1] = r1;
                b0f[np * 2 + 1][0] = r2; b0f[np * 2 + 1][1] = r3;
            }
#pragma unroll
            for (int mt = 0; mt < 2; mt++)
#pragma unroll
                for (int nt = 0; nt < 8; nt++) {
                    imma16832(acc1[mt][nt], a1f[mt], b1f[nt]);
                    imma16832(acc2[mt][nt], a1f[mt], b0f[nt]);
                    imma16832(acc2[mt][nt], a0f[mt], b1f[nt]);
                }
        }

        // ---- epilogue phase 1: fp32 H -> smem staging ----
        const int brow = t * 64;
        char* Hs = smem + I1_HS_OFF;
#pragma unroll
        for (int mt = 0; mt < 2; mt++) {
            float sa[2];
#pragma unroll
            for (int hrow = 0; hrow < 2; hrow++) {
                int grow = brow + wm + mt * 16 + (lane >> 2) + hrow * 8;
                sa[hrow] = (grow < M) ? sA[grow] : 0.f;
            }
#pragma unroll
            for (int nt = 0; nt < 8; nt++) {
                int gcol = wn + nt * 8 + (lane & 3) * 2;
                float sw0 = sW[gcol], sw1 = sW[gcol + 1];
                float bb0 = bias[gcol], bb1 = bias[gcol + 1];
#pragma unroll
                for (int hrow = 0; hrow < 2; hrow++) {
                    int rl = wm + mt * 16 + (lane >> 2) + hrow * 8;
                    if (brow + rl < M) {
                        float f0 = fmaf(65536.f, (float)acc1[mt][nt][hrow * 2 + 0],
                                        256.f * (float)acc2[mt][nt][hrow * 2 + 0]);
                        float f1 = fmaf(65536.f, (float)acc1[mt][nt][hrow * 2 + 1],
                                        256.f * (float)acc2[mt][nt][hrow * 2 + 1]);
                        float o0 = fmaxf(fmaf(sa[hrow] * sw0, f0, bb0), 0.f);
                        float o1 = fmaxf(fmaf(sa[hrow] * sw1, f1, bb1), 0.f);
                        *(float2*)(Hs + rl * I1_HROW + gcol * 4) = make_float2(o0, o1);
                    }
                }
            }
        }
        __syncthreads();

        // ---- epilogue phase 2: per-row quantize H -> H1/H0 + sH ----
#pragma unroll
        for (int rr = 0; rr < 8; rr++) {
            int rl = wid * 8 + rr;
            int grow = brow + rl;
            float4 v0 = *(const float4*)(Hs + rl * I1_HROW + lane * 32);
            float4 v1 = *(const float4*)(Hs + rl * I1_HROW + lane * 32 + 16);
            float m = fmaxf(fmaxf(fmaxf(fabsf(v0.x), fabsf(v0.y)), fmaxf(fabsf(v0.z), fabsf(v0.w))),
                            fmaxf(fmaxf(fabsf(v1.x), fabsf(v1.y)), fmaxf(fabsf(v1.z), fabsf(v1.w))));
            m = warp_max(m);
            float s_inv = (m > 1e-30f) ? 32512.f / m : 0.f;
            int q0 = __float2int_rn(v0.x * s_inv), q1 = __float2int_rn(v0.y * s_inv);
            int q2 = __float2int_rn(v0.z * s_inv), q3 = __float2int_rn(v0.w * s_inv);
            int q4 = __float2int_rn(v1.x * s_inv), q5 = __float2int_rn(v1.y * s_inv);
            int q6 = __float2int_rn(v1.z * s_inv), q7 = __float2int_rn(v1.w * s_inv);
            int h0, l0, h1, l1, h2, l2, h3, l3, h4, l4, h5, l5, h6, l6, h7, l7;
            split16(q0, h0, l0); split16(q1, h1, l1); split16(q2, h2, l2); split16(q3, h3, l3);
            split16(q4, h4, l4); split16(q5, h5, l5); split16(q6, h6, l6); split16(q7, h7, l7);
            if (grow < M) {
                *(uint2*)(H1 + (size_t)grow * 256 + lane * 8) =
                    make_uint2(pack4(h0, h1, h2, h3), pack4(h4, h5, h6, h7));
                *(uint2*)(H0 + (size_t)grow * 256 + lane * 8) =
                    make_uint2(pack4(l0, l1, l2, l3), pack4(l4, l5, l6, l7));
                if (lane == 0) sH[grow] = m * (1.f / 32512.f);
            }
        }
        buf ^= 1;
    }
}

// =============== persistent int8 GEMM 2: C = act(H @ W2^T + b2) =============
// H digits [M,256] i8. W2 digits [128,256] i8 RESIDENT. M-tile 64.
// 8 warps, warp tile 32x32 (wm=(wid&1)*32, wn=(wid>>1)*32). fp32 out.
#define I2_SROW 272
#define I2_B (128 * I2_SROW)            // 34816 per digit
#define I2_AB (64 * I2_SROW)            // 17408 per digit
#define I2_ABUF (2 * I2_AB)             // 34816 per buffer
#define I2_SMEM (2 * I2_B + 2 * I2_ABUF)   // 139264

template <bool RELU>
__global__ void __launch_bounds__(256, 1)
gemm2i(const int8_t* __restrict__ A1, const int8_t* __restrict__ A0,
       const float* __restrict__ sHv,
       const int8_t* __restrict__ B1, const int8_t* __restrict__ B0,
       const float* __restrict__ sW, const float* __restrict__ bias,
       float* __restrict__ C, int M) {
    extern __shared__ char smem[];
    const uint32_t sb = smem_u32(smem);
    const uint32_t sB1 = sb;
    const uint32_t sB0 = sb + I2_B;
    const uint32_t sA_0 = sb + 2 * I2_B;

    const int tid  = threadIdx.x;
    const int lane = tid & 31;
    const int wid  = tid >> 5;
    const int wm   = (wid & 1) * 32;
    const int wn   = (wid >> 1) * 32;

    // resident B digits: 128 rows x 256B each
#pragma unroll
    for (int i = 0; i < 8; i++) {
        int id = tid + i * 256;          // 0..2047
        int row = id >> 4, off = (id & 15) * 16;
        uint32_t sdst = (uint32_t)(row * I2_SROW + off);
        cp_async16(sB1 + sdst, B1 + (size_t)row * 256 + off, 16);
        cp_async16(sB0 + sdst, B0 + (size_t)row * 256 + off, 16);
    }

    int t = blockIdx.x;
    if (t < NT64) {
#pragma unroll
        for (int i = 0; i < 4; i++) {
            int id = tid + i * 256;      // 0..1023
            int row = id >> 4, off = (id & 15) * 16;
            int grow = t * 64 + row;
            int asz = grow < M ? 16 : 0;
            uint32_t sdst = (uint32_t)(row * I2_SROW + off);
            cp_async16(sA_0 + sdst, A1 + (size_t)grow * 256 + off, asz);
            cp_async16(sA_0 + I2_AB + sdst, A0 + (size_t)grow * 256 + off, asz);
        }
    }
    cp_commit();

    int buf = 0;
    for (; t < NT64; t += GRIDP) {
        cp_wait0();
        __syncthreads();

        int tn = t + GRIDP;
        if (tn < NT64) {
            uint32_t base = sA_0 + (buf ^ 1) * I2_ABUF;
#pragma unroll
            for (int i = 0; i < 4; i++) {
                int id = tid + i * 256;
                int row = id >> 4, off = (id & 15) * 16;
                int grow = tn * 64 + row;
                int asz = grow < M ? 16 : 0;
                uint32_t sdst = (uint32_t)(row * I2_SROW + off);
                cp_async16(base + sdst, A1 + (size_t)grow * 256 + off, asz);
                cp_async16(base + I2_AB + sdst, A0 + (size_t)grow * 256 + off, asz);
            }
        }
        cp_commit();

        const uint32_t cA1 = sA_0 + buf * I2_ABUF;
        const uint32_t cA0 = cA1 + I2_AB;
        int acc1[2][4][4], acc2[2][4][4];
#pragma unroll
        for (int i = 0; i < 2; i++)
#pragma unroll
            for (int j = 0; j < 4; j++)
#pragma unroll
                for (int k = 0; k < 4; k++) { acc1[i][j][k] = 0; acc2[i][j][k] = 0; }

#pragma unroll
        for (int kk = 0; kk < 8; kk++) {
            const uint32_t kb = (uint32_t)(kk * 32);
            uint32_t a1f[2][4], a0f[2][4];
#pragma unroll
            for (int mt = 0; mt < 2; mt++) {
                uint32_t arow = (uint32_t)(wm + mt * 16 + (lane & 15));
                uint32_t aoff = arow * I2_SROW + kb + ((lane >> 4) << 4);
                ldsm_x4(a1f[mt][0], a1f[mt][1], a1f[mt][2], a1f[mt][3], cA1 + aoff);
                ldsm_x4(a0f[mt][0], a0f[mt][1], a0f[mt][2], a0f[mt][3], cA0 + aoff);
            }
            uint32_t b1f[4][2], b0f[4][2];
#pragma unroll
            for (int np = 0; np < 2; np++) {
                int g = lane >> 3, r = lane & 7;
                uint32_t browi = (uint32_t)(wn + np * 16 + ((g & 2) ? 8 : 0) + r);
                uint32_t boff = browi * I2_SROW + kb + ((g & 1) << 4);
                uint32_t r0, r1, r2, r3;
                ldsm_x4(r0, r1, r2, r3, sB1 + boff);
                b1f[np * 2][0] = r0; b1f[np * 2][1] = r1;
                b1f[np * 2 + 1][0] = r2; b1f[np * 2 + 1][1] = r3;
                ldsm_x4(r0, r1, r2, r3, sB0 + boff);
                b0f[np * 2][0] = r0; b0f[np * 2][1] = r1;
                b0f[np * 2 + 1][0] = r2; b0f[np * 2 + 1][1] = r3;
            }
#pragma unroll
            for (int mt = 0; mt < 2; mt++)
#pragma unroll
                for (int nt = 0; nt < 4; nt++) {
                    imma16832(acc1[mt][nt], a1f[mt], b1f[nt]);
                    imma16832(acc2[mt][nt], a1f[mt], b0f[nt]);
                    imma16832(acc2[mt][nt], a0f[mt], b1f[nt]);
                }
        }

        const int brow = t * 64;
#pragma unroll
        for (int mt = 0; mt < 2; mt++) {
            float sh[2];
#pragma unroll
            for (int hrow = 0; hrow < 2; hrow++) {
                int grow = brow + wm + mt * 16 + (lane >> 2) + hrow * 8;
                sh[hrow] = (grow < M) ? sHv[grow] : 0.f;
            }
#pragma unroll
            for (int nt = 0; nt < 4; nt++) {
                int gcol = wn + nt * 8 + (lane & 3) * 2;
                float sw0 = sW[gcol], sw1 = sW[gcol + 1];
                float bb0 = bias[gcol], bb1 = bias[gcol + 1];
#pragma unroll
                for (int hrow = 0; hrow < 2; hrow++) {
                    int grow = brow + wm + mt * 16 + (lane >> 2) + hrow * 8;
                    if (grow < M) {
                        float f0 = fmaf(65536.f, (float)acc1[mt][nt][hrow * 2 + 0],
                                        256.f * (float)acc2[mt][nt][hrow * 2 + 0]);
                        float f1 = fmaf(65536.f, (float)acc1[mt][nt][hrow * 2 + 1],
                                        256.f * (float)acc2[mt][nt][hrow * 2 + 1]);
                        float o0 = fmaf(sh[hrow] * sw0, f0, bb0);
                        float o1 = fmaf(sh[hrow] * sw1, f1, bb1);
                        if (RELU) { o0 = fmaxf(o0, 0.f); o1 = fmaxf(o1, 0.f); }
                        *(float2*)(C + (size_t)grow * 128 + gcol) = make_float2(o0, o1);
                    }
                }
            }
        }
        buf ^= 1;
    }
}

// ---------------- launch ----------------
extern "C" void kernel_launch(void* const* d_in, const int* in_sizes, int n_in,
                              void* d_out, int out_size) {
    const float* x     = (const float*)d_in[0];
    const int*   ei    = (const int*)d_in[1];
    const int*   ea    = (const int*)d_in[2];
    const float* ee1_0 = (const float*)d_in[3];
    const float* ee2_0 = (const float*)d_in[4];
    const float* W1_0  = (const float*)d_in[5];
    const float* b1_0  = (const float*)d_in[6];
    const float* W2_0  = (const float*)d_in[7];
    const float* b2_0  = (const float*)d_in[8];
    const float* ee1_1 = (const float*)d_in[9];
    const float* ee2_1 = (const float*)d_in[10];
    const float* W1_1  = (const float*)d_in[11];
    const float* b1_1  = (const float*)d_in[12];
    const float* W2_1  = (const float*)d_in[13];
    const float* b2_1  = (const float*)d_in[14];
    float* out = (float*)d_out;

    const int N = in_sizes[0] / DD;
    const int E = in_sizes[1] / 2;

    float *y0, *sA, *sH, *sW;
    int8_t *A1, *A0, *H1, *H0, *WB1, *WB0;
    int* cnt;
    uint32_t* payload;
    cudaGetSymbolAddress((void**)&y0, g_y0);
    cudaGetSymbolAddress((void**)&A1, g_A1);
    cudaGetSymbolAddress((void**)&A0, g_A0);
    cudaGetSymbolAddress((void**)&sA, g_sA);
    cudaGetSymbolAddress((void**)&H1, g_H1);
    cudaGetSymbolAddress((void**)&H0, g_H0);
    cudaGetSymbolAddress((void**)&sH, g_sH);
    cudaGetSymbolAddress((void**)&WB1, g_WB1);
    cudaGetSymbolAddress((void**)&WB0, g_WB0);
    cudaGetSymbolAddress((void**)&sW, g_sW);
    cudaGetSymbolAddress((void**)&cnt, g_cnt);
    cudaGetSymbolAddress((void**)&payload, g_payload);

    cudaFuncSetAttribute(gemm1i, cudaFuncAttributeMaxDynamicSharedMemorySize, I1_SMEM);
    cudaFuncSetAttribute(gemm2i<true>, cudaFuncAttributeMaxDynamicSharedMemorySize, I2_SMEM);
    cudaFuncSetAttribute(gemm2i<false>, cudaFuncAttributeMaxDynamicSharedMemorySize, I2_SMEM);

    const int ggrid = (N + 7) / 8;

    prep_kernel<<<96 + (NN + 255) / 256, 256>>>(W1_0, W2_0, W1_1, W2_1, WB1, WB0, sW, cnt);
    fill_kernel<<<(E + 255) / 256, 256>>>(ei, ea, cnt, payload, E);

    // ============ layer 0 ============
    gather_kernel<<<ggrid, 256>>>(x, cnt, payload, ee1_0, ee2_0, A1, A0, sA, N);
    gemm1i<<<GRIDP, 256, I1_SMEM>>>(A1, A0, sA, WB1, WB0, sW, b1_0, H1, H0, sH, N);
    gemm2i<true><<<GRIDP, 256, I2_SMEM>>>(H1, H0, sH, WB1 + 32768, WB0 + 32768, sW + 256, b2_0, y0, N);

    // ============ layer 1 ============
    gather_kernel<<<ggrid, 256>>>(y0, cnt, payload, ee1_1, ee2_1, A1, A0, sA, N);
    gemm1i<<<GRIDP, 256, I1_SMEM>>>(A1, A0, sA, WB1 + 65536, WB0 + 65536, sW + 384, b1_1, H1, H0, sH, N);
    gemm2i<false><<<GRIDP, 256, I2_SMEM>>>(H1, H0, sH, WB1 + 98304, WB0 + 98304, sW + 640, b2_1, out, N);
}

// round 12
// speedup vs baseline: 1.9157x; 1.9157x over previous
#include <cuda_runtime.h>
#include <cuda_bf16.h>
#include <cstdint>

#define NN 50000
#define EE 800000
#define DD 128
#define BUCKET 64
#define GRIDP 148
#define NT32 1563            // ceil(50000/32)

// ---------------- scratch (static device globals) ----------------
__device__ float g_y0[(size_t)NN * DD];
__device__ __nv_bfloat16 g_Ahi[(size_t)NN * DD];
__device__ __nv_bfloat16 g_Alo[(size_t)NN * DD];
__device__ __nv_bfloat16 g_Hhi[(size_t)NN * 2 * DD];
__device__ __nv_bfloat16 g_Hlo[(size_t)NN * 2 * DD];
__device__ __nv_bfloat16 g_Wt[8][256 * 128];
__device__ int g_cnt[NN];
__device__ uint32_t g_payload[(size_t)NN * BUCKET];

// ---------------- PTX helpers (base ISA only) ----------------
__device__ __forceinline__ uint32_t smem_u32(const void* p) {
    uint32_t a;
    asm("{ .reg .u64 t; cvta.to.shared.u64 t, %1; cvt.u32.u64 %0, t; }" : "=r"(a) : "l"(p));
    return a;
}
__device__ __forceinline__ void cp_async16(uint32_t dst, const void* src, int srcbytes) {
    asm volatile("cp.async.cg.shared.global [%0], [%1], 16, %2;"
                 :: "r"(dst), "l"(src), "r"(srcbytes) : "memory");
}
__device__ __forceinline__ void cp_commit() { asm volatile("cp.async.commit_group;" ::: "memory"); }
__device__ __forceinline__ void cp_wait0()  { asm volatile("cp.async.wait_group 0;" ::: "memory"); }

__device__ __forceinline__ void ldsm_x4(uint32_t& r0, uint32_t& r1, uint32_t& r2, uint32_t& r3,
                                        uint32_t addr) {
    asm volatile("ldmatrix.sync.aligned.m8n8.x4.shared.b16 {%0,%1,%2,%3}, [%4];"
                 : "=r"(r0), "=r"(r1), "=r"(r2), "=r"(r3) : "r"(addr));
}
__device__ __forceinline__ void mma16816(float* d, const uint32_t* a, const uint32_t* b) {
    asm volatile(
        "mma.sync.aligned.m16n8k16.row.col.f32.bf16.bf16.f32 "
        "{%0,%1,%2,%3}, {%4,%5,%6,%7}, {%8,%9}, {%0,%1,%2,%3};"
        : "+f"(d[0]), "+f"(d[1]), "+f"(d[2]), "+f"(d[3])
        : "r"(a[0]), "r"(a[1]), "r"(a[2]), "r"(a[3]), "r"(b[0]), "r"(b[1]));
}

// ---------------- prep: weight transposes + zero cnt ----------------
__global__ void __launch_bounds__(256)
prep_kernel(const float* __restrict__ W10, const float* __restrict__ W20,
            const float* __restrict__ W11, const float* __restrict__ W21,
            __nv_bfloat16* __restrict__ wt, int* __restrict__ cnt) {
    int b = blockIdx.x;
    if (b >= 512) {
        int i = (b - 512) * 256 + threadIdx.x;
        if (i < NN) cnt[i] = 0;
        return;
    }
    int which = b >> 7;
    int i = ((b & 127) << 8) + threadIdx.x;
    const float* W;
    int K, N;
    if (which == 0)      { W = W10; K = 128; N = 256; }
    else if (which == 1) { W = W20; K = 256; N = 128; }
    else if (which == 2) { W = W11; K = 128; N = 256; }
    else                 { W = W21; K = 256; N = 128; }
    int k = i / N, n = i % N;
    float a = W[i];
    __nv_bfloat16 h = __float2bfloat16_rn(a);
    __nv_bfloat16 l = __float2bfloat16_rn(a - __bfloat162float(h));
    __nv_bfloat16* thi = wt + (size_t)(2 * which) * 32768;
    __nv_bfloat16* tlo = thi + 32768;
    thi[n * K + k] = h;
    tlo[n * K + k] = l;
}

// ---------------- bucket fill ----------------
__global__ void __launch_bounds__(256)
fill_kernel(const int* __restrict__ ei, const int* __restrict__ ea,
            int* __restrict__ cnt, uint32_t* __restrict__ payload, int E) {
    int e = blockIdx.x * 256 + threadIdx.x;
    if (e >= E) return;
    int src = ei[e];
    int dst = ei[E + e];
    int a0 = ea[2 * e];
    int a1 = ea[2 * e + 1];
    int pos = atomicAdd(&cnt[dst], 1);
    payload[((size_t)dst << 6) + pos] = (uint32_t)src | ((uint32_t)(a0 * 3 + a1) << 16);
}

// ---------------- gather -> bf16 hi/lo ----------------
__global__ void __launch_bounds__(256)
gather_kernel(const float* __restrict__ x,
              const int* __restrict__ cnt, const uint32_t* __restrict__ payload,
              const float* __restrict__ ee1, const float* __restrict__ ee2,
              __nv_bfloat16* __restrict__ Ahi, __nv_bfloat16* __restrict__ Alo,
              int N) {
    __shared__ float combo[18 * 128];
    const int tid = threadIdx.x;
#pragma unroll
    for (int k = 0; k < 9; k++) {
        int idx = tid + k * 256;
        int c = idx >> 7, d = idx & 127;
        combo[idx] = ee1[(c / 3) * 128 + d] + ee2[(c % 3) * 128 + d];
    }
    __syncthreads();

    const int lane = tid & 31;
    const int n = blockIdx.x * 8 + (tid >> 5);
    if (n >= N) return;
    const int d4 = lane * 4;

    const uint32_t* pl = payload + ((size_t)n << 6);
    int deg = cnt[n];
    float4 acc = make_float4(0.f, 0.f, 0.f, 0.f);
    int i = 0;
    for (; i + 3 < deg; i += 4) {
        uint32_t p0 = pl[i], p1 = pl[i + 1], p2 = pl[i + 2], p3 = pl[i + 3];
        float4 x0 = *(const float4*)(x + (size_t)(p0 & 0xFFFF) * 128 + d4);
        float4 x1 = *(const float4*)(x + (size_t)(p1 & 0xFFFF) * 128 + d4);
        float4 x2 = *(const float4*)(x + (size_t)(p2 & 0xFFFF) * 128 + d4);
        float4 x3 = *(const float4*)(x + (size_t)(p3 & 0xFFFF) * 128 + d4);
        float4 c0 = *(const float4*)(combo + (p0 >> 16) * 128 + d4);
        float4 c1 = *(const float4*)(combo + (p1 >> 16) * 128 + d4);
        float4 c2 = *(const float4*)(combo + (p2 >> 16) * 128 + d4);
        float4 c3 = *(const float4*)(combo + (p3 >> 16) * 128 + d4);
        acc.x += (x0.x + c0.x) + (x1.x + c1.x) + (x2.x + c2.x) + (x3.x + c3.x);
        acc.y += (x0.y + c0.y) + (x1.y + c1.y) + (x2.y + c2.y) + (x3.y + c3.y);
        acc.z += (x0.z + c0.z) + (x1.z + c1.z) + (x2.z + c2.z) + (x3.z + c3.z);
        acc.w += (x0.w + c0.w) + (x1.w + c1.w) + (x2.w + c2.w) + (x3.w + c3.w);
    }
    for (; i < deg; i++) {
        uint32_t p0 = pl[i];
        float4 x0 = *(const float4*)(x + (size_t)(p0 & 0xFFFF) * 128 + d4);
        float4 c0 = *(const float4*)(combo + (p0 >> 16) * 128 + d4);
        acc.x += x0.x + c0.x;
        acc.y += x0.y + c0.y;
        acc.z += x0.z + c0.z;
        acc.w += x0.w + c0.w;
    }

    __nv_bfloat16 h0 = __float2bfloat16_rn(acc.x), h1 = __float2bfloat16_rn(acc.y);
    __nv_bfloat16 h2 = __float2bfloat16_rn(acc.z), h3 = __float2bfloat16_rn(acc.w);
    __nv_bfloat16 l0 = __float2bfloat16_rn(acc.x - __bfloat162float(h0));
    __nv_bfloat16 l1 = __float2bfloat16_rn(acc.y - __bfloat162float(h1));
    __nv_bfloat16 l2 = __float2bfloat16_rn(acc.z - __bfloat162float(h2));
    __nv_bfloat16 l3 = __float2bfloat16_rn(acc.w - __bfloat162float(h3));
    __nv_bfloat162 hp0(h0, h1), hp1(h2, h3), lp0(l0, l1), lp1(l2, l3);
    size_t o = (size_t)n * 128 + d4;
    *(uint2*)(Ahi + o) = make_uint2(*(uint32_t*)&hp0, *(uint32_t*)&hp1);
    *(uint2*)(Alo + o) = make_uint2(*(uint32_t*)&lp0, *(uint32_t*)&lp1);
}

// =============== persistent GEMM 1: H = relu(A @ Wt1^T + b1) ================
// 512 threads = 16 warps, warp tile 16x32. M-tile 32, A double-buffered.
// Wt1 [256,128] hi/lo RESIDENT. Fragments software-pipelined across k-steps.
#define SROWB 272
#define G1_B (256 * SROWB)            // 69632 per matrix
#define G1_AB (32 * SROWB)            // 8704 per matrix
#define G1_ABUF (2 * G1_AB)           // 17408 per buffer (hi+lo)
#define G1_SMEM (2 * G1_B + 2 * G1_ABUF)   // 174080

__global__ void __launch_bounds__(512, 1)
gemm1p(const __nv_bfloat16* __restrict__ Ahi, const __nv_bfloat16* __restrict__ Alo,
       const __nv_bfloat16* __restrict__ Bhi, const __nv_bfloat16* __restrict__ Blo,
       const float* __restrict__ bias,
       __nv_bfloat16* __restrict__ Hhi, __nv_bfloat16* __restrict__ Hlo, int M) {
    extern __shared__ char smem[];
    const uint32_t sb = smem_u32(smem);
    const uint32_t sBhi = sb;
    const uint32_t sBlo = sb + G1_B;
    const uint32_t sA0  = sb + 2 * G1_B;   // buf: [Ahi | Alo]

    const int tid  = threadIdx.x;
    const int lane = tid & 31;
    const int wid  = tid >> 5;
    const int wm   = (wid & 1) * 16;
    const int wn   = (wid >> 1) * 32;

    // ---- load resident B: 256 rows x 256B, hi+lo ----
#pragma unroll
    for (int i = 0; i < 8; i++) {
        int id = tid + i * 512;
        int row = id >> 4, off = (id & 15) * 16;
        uint32_t sdst = (uint32_t)(row * SROWB + off);
        cp_async16(sBhi + sdst, (const char*)(Bhi + (size_t)row * 128) + off, 16);
        cp_async16(sBlo + sdst, (const char*)(Blo + (size_t)row * 128) + off, 16);
    }

    // ---- issue first A tile ----
    int t = blockIdx.x;
    const int arow_ld = tid >> 4;
    const int aoff_ld = (tid & 15) * 16;
    if (t < NT32) {
        int grow = t * 32 + arow_ld;
        int asz = grow < M ? 16 : 0;
        uint32_t sdst = (uint32_t)(arow_ld * SROWB + aoff_ld);
        cp_async16(sA0 + sdst, (const char*)(Ahi + (size_t)grow * 128) + aoff_ld, asz);
        cp_async16(sA0 + G1_AB + sdst, (const char*)(Alo + (size_t)grow * 128) + aoff_ld, asz);
    }
    cp_commit();

    // per-warp constant fragment addresses (k-offset added per step)
    const uint32_t a_base = (uint32_t)((wm + (lane & 15)) * SROWB + ((lane >> 4) << 4));
    const int bg = lane >> 3, br = lane & 7;
    uint32_t b_base[2];
#pragma unroll
    for (int np = 0; np < 2; np++)
        b_base[np] = (uint32_t)((wn + np * 16 + ((bg & 2) ? 8 : 0) + br) * SROWB + ((bg & 1) << 4));

    int buf = 0;
    for (; t < NT32; t += GRIDP) {
        cp_wait0();
        __syncthreads();

        // issue next tile into other buffer
        int tn = t + GRIDP;
        if (tn < NT32) {
            uint32_t base = sA0 + (buf ^ 1) * G1_ABUF;
            int grow = tn * 32 + arow_ld;
            int asz = grow < M ? 16 : 0;
            uint32_t sdst = (uint32_t)(arow_ld * SROWB + aoff_ld);
            cp_async16(base + sdst, (const char*)(Ahi + (size_t)grow * 128) + aoff_ld, asz);
            cp_async16(base + G1_AB + sdst, (const char*)(Alo + (size_t)grow * 128) + aoff_ld, asz);
        }
        cp_commit();

        const uint32_t cAhi = sA0 + buf * G1_ABUF;
        const uint32_t cAlo = cAhi + G1_AB;
        float acc[4][4];
#pragma unroll
        for (int j = 0; j < 4; j++)
#pragma unroll
            for (int k = 0; k < 4; k++) acc[j][k] = 0.f;

        // ---- software-pipelined k loop: prefetch kk+1 fragments before kk MMAs
        uint32_t ahf[2][4], alf[2][4], bhf[2][4][2], blf[2][4][2];
        {   // prologue: k-step 0 into slot 0
            ldsm_x4(ahf[0][0], ahf[0][1], ahf[0][2], ahf[0][3], cAhi + a_base);
            ldsm_x4(alf[0][0], alf[0][1], alf[0][2], alf[0][3], cAlo + a_base);
#pragma unroll
            for (int np = 0; np < 2; np++) {
                uint32_t r0, r1, r2, r3;
                ldsm_x4(r0, r1, r2, r3, sBhi + b_base[np]);
                bhf[0][np * 2][0] = r0; bhf[0][np * 2][1] = r1;
                bhf[0][np * 2 + 1][0] = r2; bhf[0][np * 2 + 1][1] = r3;
                ldsm_x4(r0, r1, r2, r3, sBlo + b_base[np]);
                blf[0][np * 2][0] = r0; blf[0][np * 2][1] = r1;
                blf[0][np * 2 + 1][0] = r2; blf[0][np * 2 + 1][1] = r3;
            }
        }
#pragma unroll
        for (int kk = 0; kk < 8; kk++) {
            const int cur = kk & 1, nxt = cur ^ 1;
            if (kk < 7) {
                const uint32_t kb = (uint32_t)((kk + 1) * 32);
                ldsm_x4(ahf[nxt][0], ahf[nxt][1], ahf[nxt][2], ahf[nxt][3], cAhi + a_base + kb);
                ldsm_x4(alf[nxt][0], alf[nxt][1], alf[nxt][2], alf[nxt][3], cAlo + a_base + kb);
#pragma unroll
                for (int np = 0; np < 2; np++) {
                    uint32_t r0, r1, r2, r3;
                    ldsm_x4(r0, r1, r2, r3, sBhi + b_base[np] + kb);
                    bhf[nxt][np * 2][0] = r0; bhf[nxt][np * 2][1] = r1;
                    bhf[nxt][np * 2 + 1][0] = r2; bhf[nxt][np * 2 + 1][1] = r3;
                    ldsm_x4(r0, r1, r2, r3, sBlo + b_base[np] + kb);
                    blf[nxt][np * 2][0] = r0; blf[nxt][np * 2][1] = r1;
                    blf[nxt][np * 2 + 1][0] = r2; blf[nxt][np * 2 + 1][1] = r3;
                }
            }
#pragma unroll
            for (int nt = 0; nt < 4; nt++) {
                mma16816(acc[nt], ahf[cur], bhf[cur][nt]);
                mma16816(acc[nt], ahf[cur], blf[cur][nt]);
                mma16816(acc[nt], alf[cur], bhf[cur][nt]);
            }
        }

        // ---- epilogue: bias+relu, hi/lo split ----
        const int brow = t * 32;
#pragma unroll
        for (int nt = 0; nt < 4; nt++) {
            int gcol = wn + nt * 8 + (lane & 3) * 2;
            float b0 = bias[gcol], b1 = bias[gcol + 1];
#pragma unroll
            for (int hrow = 0; hrow < 2; hrow++) {
                int grow = brow + wm + (lane >> 2) + hrow * 8;
                if (grow < M) {
                    float o0 = fmaxf(acc[nt][hrow * 2 + 0] + b0, 0.f);
                    float o1 = fmaxf(acc[nt][hrow * 2 + 1] + b1, 0.f);
                    __nv_bfloat16 h0 = __float2bfloat16_rn(o0);
                    __nv_bfloat16 h1 = __float2bfloat16_rn(o1);
                    __nv_bfloat16 l0 = __float2bfloat16_rn(o0 - __bfloat162float(h0));
                    __nv_bfloat16 l1 = __float2bfloat16_rn(o1 - __bfloat162float(h1));
                    __nv_bfloat162 hp(h0, h1), lp(l0, l1);
                    size_t o = (size_t)grow * 256 + gcol;
                    *(__nv_bfloat162*)(Hhi + o) = hp;
                    *(__nv_bfloat162*)(Hlo + o) = lp;
                }
            }
        }
        buf ^= 1;
    }
}

// =============== persistent GEMM 2: C = act(H @ Wt2^T + b2) =================
// 512 threads = 16 warps, warp tile 16x16. M-tile 32, K=256, pipelined frags.
#define SROW2 528
#define G2_B (128 * SROW2)            // 67584 per matrix
#define G2_AB (32 * SROW2)            // 16896 per matrix
#define G2_ABUF (2 * G2_AB)           // 33792 per buffer
#define G2_SMEM (2 * G2_B + 2 * G2_ABUF)   // 202752

template <bool RELU>
__global__ void __launch_bounds__(512, 1)
gemm2p(const __nv_bfloat16* __restrict__ Ahi, const __nv_bfloat16* __restrict__ Alo,
       const __nv_bfloat16* __restrict__ Bhi, const __nv_bfloat16* __restrict__ Blo,
       const float* __restrict__ bias, float* __restrict__ C, int M) {
    extern __shared__ char smem[];
    const uint32_t sb = smem_u32(smem);
    const uint32_t sBhi = sb;
    const uint32_t sBlo = sb + G2_B;
    const uint32_t sA0  = sb + 2 * G2_B;

    const int tid  = threadIdx.x;
    const int lane = tid & 31;
    const int wid  = tid >> 5;
    const int wm   = (wid & 1) * 16;
    const int wn   = (wid >> 1) * 16;

    // ---- load resident B: 128 rows x 512B, hi+lo ----
#pragma unroll
    for (int i = 0; i < 8; i++) {
        int id = tid + i * 512;
        int row = id >> 5, off = (id & 31) * 16;
        uint32_t sdst = (uint32_t)(row * SROW2 + off);
        cp_async16(sBhi + sdst, (const char*)(Bhi + (size_t)row * 256) + off, 16);
        cp_async16(sBlo + sdst, (const char*)(Blo + (size_t)row * 256) + off, 16);
    }

    int t = blockIdx.x;
    if (t < NT32) {
#pragma unroll
        for (int i = 0; i < 2; i++) {
            int id = tid + i * 512;
            int row = id >> 5, off = (id & 31) * 16;
            int grow = t * 32 + row;
            int asz = grow < M ? 16 : 0;
            uint32_t sdst = (uint32_t)(row * SROW2 + off);
            cp_async16(sA0 + sdst, (const char*)(Ahi + (size_t)grow * 256) + off, asz);
            cp_async16(sA0 + G2_AB + sdst, (const char*)(Alo + (size_t)grow * 256) + off, asz);
        }
    }
    cp_commit();

    const uint32_t a_base = (uint32_t)((wm + (lane & 15)) * SROW2 + ((lane >> 4) << 4));
    const int bg = lane >> 3, br = lane & 7;
    const uint32_t b_base = (uint32_t)((wn + ((bg & 2) ? 8 : 0) + br) * SROW2 + ((bg & 1) << 4));

    int buf = 0;
    for (; t < NT32; t += GRIDP) {
        cp_wait0();
        __syncthreads();

        int tn = t + GRIDP;
        if (tn < NT32) {
            uint32_t base = sA0 + (buf ^ 1) * G2_ABUF;
#pragma unroll
            for (int i = 0; i < 2; i++) {
                int id = tid + i * 512;
                int row = id >> 5, off = (id & 31) * 16;
                int grow = tn * 32 + row;
                int asz = grow < M ? 16 : 0;
                uint32_t sdst = (uint32_t)(row * SROW2 + off);
                cp_async16(base + sdst, (const char*)(Ahi + (size_t)grow * 256) + off, asz);
                cp_async16(base + G2_AB + sdst, (const char*)(Alo + (size_t)grow * 256) + off, asz);
            }
        }
        cp_commit();

        const uint32_t cAhi = sA0 + buf * G2_ABUF;
        const uint32_t cAlo = cAhi + G2_AB;
        float acc[2][4];
#pragma unroll
        for (int j = 0; j < 2; j++)
#pragma unroll
            for (int k = 0; k < 4; k++) acc[j][k] = 0.f;

        uint32_t ahf[2][4], alf[2][4], bhf[2][2][2], blf[2][2][2];
        {
            ldsm_x4(ahf[0][0], ahf[0][1], ahf[0][2], ahf[0][3], cAhi + a_base);
            ldsm_x4(alf[0][0], alf[0][1], alf[0][2], alf[0][3], cAlo + a_base);
            uint32_t r0, r1, r2, r3;
            ldsm_x4(r0, r1, r2, r3, sBhi + b_base);
            bhf[0][0][0] = r0; bhf[0][0][1] = r1; bhf[0][1][0] = r2; bhf[0][1][1] = r3;
            ldsm_x4(r0, r1, r2, r3, sBlo + b_base);
            blf[0][0][0] = r0; blf[0][0][1] = r1; blf[0][1][0] = r2; blf[0][1][1] = r3;
        }
#pragma unroll
        for (int kk = 0; kk < 16; kk++) {
            const int cur = kk & 1, nxt = cur ^ 1;
            if (kk < 15) {
                const uint32_t kb = (uint32_t)((kk + 1) * 32);
                ldsm_x4(ahf[nxt][0], ahf[nxt][1], ahf[nxt][2], ahf[nxt][3], cAhi + a_base + kb);
                ldsm_x4(alf[nxt][0], alf[nxt][1], alf[nxt][2], alf[nxt][3], cAlo + a_base + kb);
                uint32_t r0, r1, r2, r3;
                ldsm_x4(r0, r1, r2, r3, sBhi + b_base + kb);
                bhf[nxt][0][0] = r0; bhf[nxt][0][1] = r1; bhf[nxt][1][0] = r2; bhf[nxt][1][1] = r3;
                ldsm_x4(r0, r1, r2, r3, sBlo + b_base + kb);
                blf[nxt][0][0] = r0; blf[nxt][0][1] = r1; blf[nxt][1][0] = r2; blf[nxt][1][1] = r3;
            }
#pragma unroll
            for (int nt = 0; nt < 2; nt++) {
                mma16816(acc[nt], ahf[cur], bhf[cur][nt]);
                mma16816(acc[nt], ahf[cur], blf[cur][nt]);
                mma16816(acc[nt], alf[cur], bhf[cur][nt]);
            }
        }

        const int brow = t * 32;
#pragma unroll
        for (int nt = 0; nt < 2; nt++) {
            int gcol = wn + nt * 8 + (lane & 3) * 2;
            float b0 = bias[gcol], b1 = bias[gcol + 1];
#pragma unroll
            for (int hrow = 0; hrow < 2; hrow++) {
                int grow = brow + wm + (lane >> 2) + hrow * 8;
                if (grow < M) {
                    float o0 = acc[nt][hrow * 2 + 0] + b0;
                    float o1 = acc[nt][hrow * 2 + 1] + b1;
                    if (RELU) { o0 = fmaxf(o0, 0.f); o1 = fmaxf(o1, 0.f); }
                    *(float2*)(C + (size_t)grow * 128 + gcol) = make_float2(o0, o1);
                }
            }
        }
        buf ^= 1;
    }
}

// ---------------- launch ----------------
extern "C" void kernel_launch(void* const* d_in, const int* in_sizes, int n_in,
                              void* d_out, int out_size) {
    const float* x     = (const float*)d_in[0];
    const int*   ei    = (const int*)d_in[1];
    const int*   ea    = (const int*)d_in[2];
    const float* ee1_0 = (const float*)d_in[3];
    const float* ee2_0 = (const float*)d_in[4];
    const float* W1_0  = (const float*)d_in[5];
    const float* b1_0  = (const float*)d_in[6];
    const float* W2_0  = (const float*)d_in[7];
    const float* b2_0  = (const float*)d_in[8];
    const float* ee1_1 = (const float*)d_in[9];
    const float* ee2_1 = (const float*)d_in[10];
    const float* W1_1  = (const float*)d_in[11];
    const float* b1_1  = (const float*)d_in[12];
    const float* W2_1  = (const float*)d_in[13];
    const float* b2_1  = (const float*)d_in[14];
    float* out = (float*)d_out;

    const int N = in_sizes[0] / DD;
    const int E = in_sizes[1] / 2;

    float *y0;
    __nv_bfloat16 *Ahi, *Alo, *Hhi, *Hlo, *Wt;
    int* cnt;
    uint32_t* payload;
    cudaGetSymbolAddress((void**)&y0, g_y0);
    cudaGetSymbolAddress((void**)&Ahi, g_Ahi);
    cudaGetSymbolAddress((void**)&Alo, g_Alo);
    cudaGetSymbolAddress((void**)&Hhi, g_Hhi);
    cudaGetSymbolAddress((void**)&Hlo, g_Hlo);
    cudaGetSymbolAddress((void**)&Wt, g_Wt);
    cudaGetSymbolAddress((void**)&cnt, g_cnt);
    cudaGetSymbolAddress((void**)&payload, g_payload);

    cudaFuncSetAttribute(gemm1p, cudaFuncAttributeMaxDynamicSharedMemorySize, G1_SMEM);
    cudaFuncSetAttribute(gemm2p<true>, cudaFuncAttributeMaxDynamicSharedMemorySize, G2_SMEM);
    cudaFuncSetAttribute(gemm2p<false>, cudaFuncAttributeMaxDynamicSharedMemorySize, G2_SMEM);

    const int ggrid = (N + 7) / 8;

    prep_kernel<<<512 + (NN + 255) / 256, 256>>>(W1_0, W2_0, W1_1, W2_1, Wt, cnt);
    fill_kernel<<<(E + 255) / 256, 256>>>(ei, ea, cnt, payload, E);

    // ============ layer 0 ============
    gather_kernel<<<ggrid, 256>>>(x, cnt, payload, ee1_0, ee2_0, Ahi, Alo, N);
    gemm1p<<<GRIDP, 512, G1_SMEM>>>(Ahi, Alo, Wt + 0 * 32768, Wt + 1 * 32768, b1_0, Hhi, Hlo, N);
    gemm2p<true><<<GRIDP, 512, G2_SMEM>>>(Hhi, Hlo, Wt + 2 * 32768, Wt + 3 * 32768, b2_0, y0, N);

    // ============ layer 1 ============
    gather_kernel<<<ggrid, 256>>>(y0, cnt, payload, ee1_1, ee2_1, Ahi, Alo, N);
    gemm1p<<<GRIDP, 512, G1_SMEM>>>(Ahi, Alo, Wt + 4 * 32768, Wt + 5 * 32768, b1_1, Hhi, Hlo, N);
    gemm2p<false><<<GRIDP, 512, G2_SMEM>>>(Hhi, Hlo, Wt + 6 * 32768, Wt + 7 * 32768, b2_1, out, N);
}

// round 13
// speedup vs baseline: 2.2525x; 1.1758x over previous
#include <cuda_runtime.h>
#include <cuda_fp16.h>
#include <cstdint>

#define NN 50000
#define EE 800000
#define DD 128
#define BUCKET 64
#define GRIDP 148
#define NT32 1563            // ceil(50000/32)

// ---------------- scratch (static device globals) ----------------
__device__ float g_y0[(size_t)NN * DD];
__device__ __half g_A[(size_t)NN * DD];          // fp16 aggr
__device__ __half g_H[(size_t)NN * 2 * DD];      // fp16 hidden
__device__ __half g_Wt[8][256 * 128];            // [hi,lo]x{W1_0,W2_0,W1_1,W2_1}, lo pre-scaled x4096
__device__ int g_cnt[NN];
__device__ uint32_t g_payload[(size_t)NN * BUCKET];

// ---------------- PTX helpers (base ISA only) ----------------
__device__ __forceinline__ uint32_t smem_u32(const void* p) {
    uint32_t a;
    asm("{ .reg .u64 t; cvta.to.shared.u64 t, %1; cvt.u32.u64 %0, t; }" : "=r"(a) : "l"(p));
    return a;
}
__device__ __forceinline__ void cp_async16(uint32_t dst, const void* src, int srcbytes) {
    asm volatile("cp.async.cg.shared.global [%0], [%1], 16, %2;"
                 :: "r"(dst), "l"(src), "r"(srcbytes) : "memory");
}
__device__ __forceinline__ void cp_commit() { asm volatile("cp.async.commit_group;" ::: "memory"); }
__device__ __forceinline__ void cp_wait0()  { asm volatile("cp.async.wait_group 0;" ::: "memory"); }

__device__ __forceinline__ void ldsm_x4(uint32_t& r0, uint32_t& r1, uint32_t& r2, uint32_t& r3,
                                        uint32_t addr) {
    asm volatile("ldmatrix.sync.aligned.m8n8.x4.shared.b16 {%0,%1,%2,%3}, [%4];"
                 : "=r"(r0), "=r"(r1), "=r"(r2), "=r"(r3) : "r"(addr));
}
__device__ __forceinline__ void mma16816(float* d, const uint32_t* a, const uint32_t* b) {
    asm volatile(
        "mma.sync.aligned.m16n8k16.row.col.f32.f16.f16.f32 "
        "{%0,%1,%2,%3}, {%4,%5,%6,%7}, {%8,%9}, {%0,%1,%2,%3};"
        : "+f"(d[0]), "+f"(d[1]), "+f"(d[2]), "+f"(d[3])
        : "r"(a[0]), "r"(a[1]), "r"(a[2]), "r"(a[3]), "r"(b[0]), "r"(b[1]));
}

// ---------------- prep: weight transposes (fp16 hi + lo*4096) + zero cnt ----
__global__ void __launch_bounds__(256)
prep_kernel(const float* __restrict__ W10, const float* __restrict__ W20,
            const float* __restrict__ W11, const float* __restrict__ W21,
            __half* __restrict__ wt, int* __restrict__ cnt) {
    int b = blockIdx.x;
    if (b >= 512) {
        int i = (b - 512) * 256 + threadIdx.x;
        if (i < NN) cnt[i] = 0;
        return;
    }
    int which = b >> 7;
    int i = ((b & 127) << 8) + threadIdx.x;
    const float* W;
    int K, N;
    if (which == 0)      { W = W10; K = 128; N = 256; }
    else if (which == 1) { W = W20; K = 256; N = 128; }
    else if (which == 2) { W = W11; K = 128; N = 256; }
    else                 { W = W21; K = 256; N = 128; }
    int k = i / N, n = i % N;
    float a = W[i];
    __half h = __float2half_rn(a);
    __half l = __float2half_rn((a - __half2float(h)) * 4096.f);
    __half* thi = wt + (size_t)(2 * which) * 32768;
    __half* tlo = thi + 32768;
    thi[n * K + k] = h;
    tlo[n * K + k] = l;
}

// ---------------- bucket fill ----------------
__global__ void __launch_bounds__(256)
fill_kernel(const int* __restrict__ ei, const int* __restrict__ ea,
            int* __restrict__ cnt, uint32_t* __restrict__ payload, int E) {
    int e = blockIdx.x * 256 + threadIdx.x;
    if (e >= E) return;
    int src = ei[e];
    int dst = ei[E + e];
    int a0 = ea[2 * e];
    int a1 = ea[2 * e + 1];
    int pos = atomicAdd(&cnt[dst], 1);
    payload[((size_t)dst << 6) + pos] = (uint32_t)src | ((uint32_t)(a0 * 3 + a1) << 16);
}

// ---------------- gather -> fp16 ----------------
__global__ void __launch_bounds__(256)
gather_kernel(const float* __restrict__ x,
              const int* __restrict__ cnt, const uint32_t* __restrict__ payload,
              const float* __restrict__ ee1, const float* __restrict__ ee2,
              __half* __restrict__ A, int N) {
    __shared__ float combo[18 * 128];
    const int tid = threadIdx.x;
#pragma unroll
    for (int k = 0; k < 9; k++) {
        int idx = tid + k * 256;
        int c = idx >> 7, d = idx & 127;
        combo[idx] = ee1[(c / 3) * 128 + d] + ee2[(c % 3) * 128 + d];
    }
    __syncthreads();

    const int lane = tid & 31;
    const int n = blockIdx.x * 8 + (tid >> 5);
    if (n >= N) return;
    const int d4 = lane * 4;

    const uint32_t* pl = payload + ((size_t)n << 6);
    int deg = cnt[n];
    float4 acc = make_float4(0.f, 0.f, 0.f, 0.f);
    int i = 0;
    for (; i + 3 < deg; i += 4) {
        uint32_t p0 = pl[i], p1 = pl[i + 1], p2 = pl[i + 2], p3 = pl[i + 3];
        float4 x0 = *(const float4*)(x + (size_t)(p0 & 0xFFFF) * 128 + d4);
        float4 x1 = *(const float4*)(x + (size_t)(p1 & 0xFFFF) * 128 + d4);
        float4 x2 = *(const float4*)(x + (size_t)(p2 & 0xFFFF) * 128 + d4);
        float4 x3 = *(const float4*)(x + (size_t)(p3 & 0xFFFF) * 128 + d4);
        float4 c0 = *(const float4*)(combo + (p0 >> 16) * 128 + d4);
        float4 c1 = *(const float4*)(combo + (p1 >> 16) * 128 + d4);
        float4 c2 = *(const float4*)(combo + (p2 >> 16) * 128 + d4);
        float4 c3 = *(const float4*)(combo + (p3 >> 16) * 128 + d4);
        acc.x += (x0.x + c0.x) + (x1.x + c1.x) + (x2.x + c2.x) + (x3.x + c3.x);
        acc.y += (x0.y + c0.y) + (x1.y + c1.y) + (x2.y + c2.y) + (x3.y + c3.y);
        acc.z += (x0.z + c0.z) + (x1.z + c1.z) + (x2.z + c2.z) + (x3.z + c3.z);
        acc.w += (x0.w + c0.w) + (x1.w + c1.w) + (x2.w + c2.w) + (x3.w + c3.w);
    }
    for (; i < deg; i++) {
        uint32_t p0 = pl[i];
        float4 x0 = *(const float4*)(x + (size_t)(p0 & 0xFFFF) * 128 + d4);
        float4 c0 = *(const float4*)(combo + (p0 >> 16) * 128 + d4);
        acc.x += x0.x + c0.x;
        acc.y += x0.y + c0.y;
        acc.z += x0.z + c0.z;
        acc.w += x0.w + c0.w;
    }

    __half2 h01 = __floats2half2_rn(acc.x, acc.y);
    __half2 h23 = __floats2half2_rn(acc.z, acc.w);
    *(uint2*)(A + (size_t)n * 128 + d4) =
        make_uint2(*(uint32_t*)&h01, *(uint32_t*)&h23);
}

// =============== persistent GEMM 1: H = relu(A @ Wt1^T + b1) ================
// 512 threads = 16 warps, warp tile 16x32. A fp16 single digit (M-tile 32,
// double-buffered). Wt1 [256,128] hi+lo' RESIDENT. 2-pass fp16 MMA.
#define SROWB 272
#define G1_B (256 * SROWB)            // 69632 per matrix
#define G1_AB (32 * SROWB)            // 8704 per buffer (single digit)
#define G1_SMEM (2 * G1_B + 2 * G1_AB)   // 156672

__global__ void __launch_bounds__(512, 1)
gemm1p(const __half* __restrict__ A,
       const __half* __restrict__ Bhi, const __half* __restrict__ Blo,
       const float* __restrict__ bias,
       __half* __restrict__ H, int M) {
    extern __shared__ char smem[];
    const uint32_t sb = smem_u32(smem);
    const uint32_t sBhi = sb;
    const uint32_t sBlo = sb + G1_B;
    const uint32_t sA0  = sb + 2 * G1_B;

    const int tid  = threadIdx.x;
    const int lane = tid & 31;
    const int wid  = tid >> 5;
    const int wm   = (wid & 1) * 16;
    const int wn   = (wid >> 1) * 32;

    // ---- load resident B: 256 rows x 256B, hi+lo ----
#pragma unroll
    for (int i = 0; i < 8; i++) {
        int id = tid + i * 512;
        int row = id >> 4, off = (id & 15) * 16;
        uint32_t sdst = (uint32_t)(row * SROWB + off);
        cp_async16(sBhi + sdst, (const char*)(Bhi + (size_t)row * 128) + off, 16);
        cp_async16(sBlo + sdst, (const char*)(Blo + (size_t)row * 128) + off, 16);
    }

    // ---- issue first A tile: 32 rows x 256B ----
    int t = blockIdx.x;
    const int arow_ld = tid >> 4;
    const int aoff_ld = (tid & 15) * 16;
    if (t < NT32) {
        int grow = t * 32 + arow_ld;
        int asz = grow < M ? 16 : 0;
        uint32_t sdst = (uint32_t)(arow_ld * SROWB + aoff_ld);
        cp_async16(sA0 + sdst, (const char*)(A + (size_t)grow * 128) + aoff_ld, asz);
    }
    cp_commit();

    const uint32_t a_base = (uint32_t)((wm + (lane & 15)) * SROWB + ((lane >> 4) << 4));
    const int bg = lane >> 3, br = lane & 7;
    uint32_t b_base[2];
#pragma unroll
    for (int np = 0; np < 2; np++)
        b_base[np] = (uint32_t)((wn + np * 16 + ((bg & 2) ? 8 : 0) + br) * SROWB + ((bg & 1) << 4));

    int buf = 0;
    for (; t < NT32; t += GRIDP) {
        cp_wait0();
        __syncthreads();

        int tn = t + GRIDP;
        if (tn < NT32) {
            uint32_t base = sA0 + (buf ^ 1) * G1_AB;
            int grow = tn * 32 + arow_ld;
            int asz = grow < M ? 16 : 0;
            uint32_t sdst = (uint32_t)(arow_ld * SROWB + aoff_ld);
            cp_async16(base + sdst, (const char*)(A + (size_t)grow * 128) + aoff_ld, asz);
        }
        cp_commit();

        const uint32_t cA = sA0 + buf * G1_AB;
        float acc1[4][4], acc2[4][4];
#pragma unroll
        for (int j = 0; j < 4; j++)
#pragma unroll
            for (int k = 0; k < 4; k++) { acc1[j][k] = 0.f; acc2[j][k] = 0.f; }

#pragma unroll
        for (int kk = 0; kk < 8; kk++) {
            const uint32_t kb = (uint32_t)(kk * 32);
            uint32_t af[4];
            ldsm_x4(af[0], af[1], af[2], af[3], cA + a_base + kb);
            uint32_t bh[4][2], bl[4][2];
#pragma unroll
            for (int np = 0; np < 2; np++) {
                uint32_t r0, r1, r2, r3;
                ldsm_x4(r0, r1, r2, r3, sBhi + b_base[np] + kb);
                bh[np * 2][0] = r0; bh[np * 2][1] = r1;
                bh[np * 2 + 1][0] = r2; bh[np * 2 + 1][1] = r3;
                ldsm_x4(r0, r1, r2, r3, sBlo + b_base[np] + kb);
                bl[np * 2][0] = r0; bl[np * 2][1] = r1;
                bl[np * 2 + 1][0] = r2; bl[np * 2 + 1][1] = r3;
            }
#pragma unroll
            for (int nt = 0; nt < 4; nt++) {
                mma16816(acc1[nt], af, bh[nt]);
                mma16816(acc2[nt], af, bl[nt]);
            }
        }

        // ---- epilogue: D = acc1 + acc2/4096 + bias, relu, fp16 store ----
        const int brow = t * 32;
#pragma unroll
        for (int nt = 0; nt < 4; nt++) {
            int gcol = wn + nt * 8 + (lane & 3) * 2;
            float b0 = bias[gcol], b1 = bias[gcol + 1];
#pragma unroll
            for (int hrow = 0; hrow < 2; hrow++) {
                int grow = brow + wm + (lane >> 2) + hrow * 8;
                if (grow < M) {
                    float o0 = fmaxf(fmaf(acc2[nt][hrow * 2 + 0], 1.f / 4096.f,
                                          acc1[nt][hrow * 2 + 0]) + b0, 0.f);
                    float o1 = fmaxf(fmaf(acc2[nt][hrow * 2 + 1], 1.f / 4096.f,
                                          acc1[nt][hrow * 2 + 1]) + b1, 0.f);
                    __half2 hp = __floats2half2_rn(o0, o1);
                    *(__half2*)(H + (size_t)grow * 256 + gcol) = hp;
                }
            }
        }
        buf ^= 1;
    }
}

// =============== persistent GEMM 2: C = act(H @ Wt2^T + b2) =================
// 512 threads = 16 warps, warp tile 16x16. H fp16 single digit (M-tile 32,
// double-buffered, K=256). Wt2 [128,256] hi+lo' RESIDENT. 2-pass fp16 MMA.
#define SROW2 528
#define G2_B (128 * SROW2)            // 67584 per matrix
#define G2_AB (32 * SROW2)            // 16896 per buffer
#define G2_SMEM (2 * G2_B + 2 * G2_AB)   // 168960

template <bool RELU>
__global__ void __launch_bounds__(512, 1)
gemm2p(const __half* __restrict__ A,
       const __half* __restrict__ Bhi, const __half* __restrict__ Blo,
       const float* __restrict__ bias, float* __restrict__ C, int M) {
    extern __shared__ char smem[];
    const uint32_t sb = smem_u32(smem);
    const uint32_t sBhi = sb;
    const uint32_t sBlo = sb + G2_B;
    const uint32_t sA0  = sb + 2 * G2_B;

    const int tid  = threadIdx.x;
    const int lane = tid & 31;
    const int wid  = tid >> 5;
    const int wm   = (wid & 1) * 16;
    const int wn   = (wid >> 1) * 16;

    // ---- load resident B: 128 rows x 512B, hi+lo ----
#pragma unroll
    for (int i = 0; i < 8; i++) {
        int id = tid + i * 512;
        int row = id >> 5, off = (id & 31) * 16;
        uint32_t sdst = (uint32_t)(row * SROW2 + off);
        cp_async16(sBhi + sdst, (const char*)(Bhi + (size_t)row * 256) + off, 16);
        cp_async16(sBlo + sdst, (const char*)(Blo + (size_t)row * 256) + off, 16);
    }

    int t = blockIdx.x;
    if (t < NT32) {
        int id = tid;                        // 512 x 16B = 8192... need 16384
#pragma unroll
        for (int i = 0; i < 2; i++) {
            int id2 = id + i * 512;
            int row = id2 >> 5, off = (id2 & 31) * 16;
            int grow = t * 32 + row;
            int asz = grow < M ? 16 : 0;
            uint32_t sdst = (uint32_t)(row * SROW2 + off);
            cp_async16(sA0 + sdst, (const char*)(A + (size_t)grow * 256) + off, asz);
        }
    }
    cp_commit();

    const uint32_t a_base = (uint32_t)((wm + (lane & 15)) * SROW2 + ((lane >> 4) << 4));
    const int bg = lane >> 3, br = lane & 7;
    const uint32_t b_base = (uint32_t)((wn + ((bg & 2) ? 8 : 0) + br) * SROW2 + ((bg & 1) << 4));

    int buf = 0;
    for (; t < NT32; t += GRIDP) {
        cp_wait0();
        __syncthreads();

        int tn = t + GRIDP;
        if (tn < NT32) {
            uint32_t base = sA0 + (buf ^ 1) * G2_AB;
#pragma unroll
            for (int i = 0; i < 2; i++) {
                int id2 = tid + i * 512;
                int row = id2 >> 5, off = (id2 & 31) * 16;
                int grow = tn * 32 + row;
                int asz = grow < M ? 16 : 0;
                uint32_t sdst = (uint32_t)(row * SROW2 + off);
                cp_async16(base + sdst, (const char*)(A + (size_t)grow * 256) + off, asz);
            }
        }
        cp_commit();

        const uint32_t cA = sA0 + buf * G2_AB;
        float acc1[2][4], acc2[2][4];
#pragma unroll
        for (int j = 0; j < 2; j++)
#pragma unroll
            for (int k = 0; k < 4; k++) { acc1[j][k] = 0.f; acc2[j][k] = 0.f; }

#pragma unroll
        for (int kk = 0; kk < 16; kk++) {
            const uint32_t kb = (uint32_t)(kk * 32);
            uint32_t af[4];
            ldsm_x4(af[0], af[1], af[2], af[3], cA + a_base + kb);
            uint32_t bh[2][2], bl[2][2];
            {
                uint32_t r0, r1, r2, r3;
                ldsm_x4(r0, r1, r2, r3, sBhi + b_base + kb);
                bh[0][0] = r0; bh[0][1] = r1; bh[1][0] = r2; bh[1][1] = r3;
                ldsm_x4(r0, r1, r2, r3, sBlo + b_base + kb);
                bl[0][0] = r0; bl[0][1] = r1; bl[1][0] = r2; bl[1][1] = r3;
            }
#pragma unroll
            for (int nt = 0; nt < 2; nt++) {
                mma16816(acc1[nt], af, bh[nt]);
                mma16816(acc2[nt], af, bl[nt]);
            }
        }

        const int brow = t * 32;
#pragma unroll
        for (int nt = 0; nt < 2; nt++) {
            int gcol = wn + nt * 8 + (lane & 3) * 2;
            float b0 = bias[gcol], b1 = bias[gcol + 1];
#pragma unroll
            for (int hrow = 0; hrow < 2; hrow++) {
                int grow = brow + wm + (lane >> 2) + hrow * 8;
                if (grow < M) {
                    float o0 = fmaf(acc2[nt][hrow * 2 + 0], 1.f / 4096.f,
                                    acc1[nt][hrow * 2 + 0]) + b0;
                    float o1 = fmaf(acc2[nt][hrow * 2 + 1], 1.f / 4096.f,
                                    acc1[nt][hrow * 2 + 1]) + b1;
                    if (RELU) { o0 = fmaxf(o0, 0.f); o1 = fmaxf(o1, 0.f); }
                    *(float2*)(C + (size_t)grow * 128 + gcol) = make_float2(o0, o1);
                }
            }
        }
        buf ^= 1;
    }
}

// ---------------- launch ----------------
extern "C" void kernel_launch(void* const* d_in, const int* in_sizes, int n_in,
                              void* d_out, int out_size) {
    const float* x     = (const float*)d_in[0];
    const int*   ei    = (const int*)d_in[1];
    const int*   ea    = (const int*)d_in[2];
    const float* ee1_0 = (const float*)d_in[3];
    const float* ee2_0 = (const float*)d_in[4];
    const float* W1_0  = (const float*)d_in[5];
    const float* b1_0  = (const float*)d_in[6];
    const float* W2_0  = (const float*)d_in[7];
    const float* b2_0  = (const float*)d_in[8];
    const float* ee1_1 = (const float*)d_in[9];
    const float* ee2_1 = (const float*)d_in[10];
    const float* W1_1  = (const float*)d_in[11];
    const float* b1_1  = (const float*)d_in[12];
    const float* W2_1  = (const float*)d_in[13];
    const float* b2_1  = (const float*)d_in[14];
    float* out = (float*)d_out;

    const int N = in_sizes[0] / DD;
    const int E = in_sizes[1] / 2;

    float *y0;
    __half *A, *H, *Wt;
    int* cnt;
    uint32_t* payload;
    cudaGetSymbolAddress((void**)&y0, g_y0);
    cudaGetSymbolAddress((void**)&A, g_A);
    cudaGetSymbolAddress((void**)&H, g_H);
    cudaGetSymbolAddress((void**)&Wt, g_Wt);
    cudaGetSymbolAddress((void**)&cnt, g_cnt);
    cudaGetSymbolAddress((void**)&payload, g_payload);

    cudaFuncSetAttribute(gemm1p, cudaFuncAttributeMaxDynamicSharedMemorySize, G1_SMEM);
    cudaFuncSetAttribute(gemm2p<true>, cudaFuncAttributeMaxDynamicSharedMemorySize, G2_SMEM);
    cudaFuncSetAttribute(gemm2p<false>, cudaFuncAttributeMaxDynamicSharedMemorySize, G2_SMEM);

    const int ggrid = (N + 7) / 8;

    prep_kernel<<<512 + (NN + 255) / 256, 256>>>(W1_0, W2_0, W1_1, W2_1, Wt, cnt);
    fill_kernel<<<(E + 255) / 256, 256>>>(ei, ea, cnt, payload, E);

    // ============ layer 0 ============
    gather_kernel<<<ggrid, 256>>>(x, cnt, payload, ee1_0, ee2_0, A, N);
    gemm1p<<<GRIDP, 512, G1_SMEM>>>(A, Wt + 0 * 32768, Wt + 1 * 32768, b1_0, H, N);
    gemm2p<true><<<GRIDP, 512, G2_SMEM>>>(H, Wt + 2 * 32768, Wt + 3 * 32768, b2_0, y0, N);

    // ============ layer 1 ============
    gather_kernel<<<ggrid, 256>>>(y0, cnt, payload, ee1_1, ee2_1, A, N);
    gemm1p<<<GRIDP, 512, G1_SMEM>>>(A, Wt + 4 * 32768, Wt + 5 * 32768, b1_1, H, N);
    gemm2p<false><<<GRIDP, 512, G2_SMEM>>>(H, Wt + 6 * 32768, Wt + 7 * 32768, b2_1, out, N);
}

// round 14
// speedup vs baseline: 2.2536x; 1.0005x over previous
#include <cuda_runtime.h>
#include <cuda_fp16.h>
#include <cstdint>

#define NN 50000
#define EE 800000
#define DD 128
#define BUCKET 64
#define GRIDP 148
#define NT32 1563            // ceil(50000/32)
#define ZB 196               // ceil(NN/256)
#define XCB 3125             // (NN*128)/(256*8)

// ---------------- scratch (static device globals) ----------------
__device__ __half g_x16[(size_t)NN * DD];        // fp16 node features (x, then y0)
__device__ __half g_A[(size_t)NN * DD];          // fp16 aggr
__device__ __half g_H[(size_t)NN * 2 * DD];      // fp16 hidden
__device__ __half g_Wt[8][256 * 128];            // [hi,lo]x4, lo pre-scaled x4096
__device__ int g_cnt[NN];
__device__ uint32_t g_payload[(size_t)NN * BUCKET];

// ---------------- PTX helpers (base ISA only) ----------------
__device__ __forceinline__ uint32_t smem_u32(const void* p) {
    uint32_t a;
    asm("{ .reg .u64 t; cvta.to.shared.u64 t, %1; cvt.u32.u64 %0, t; }" : "=r"(a) : "l"(p));
    return a;
}
__device__ __forceinline__ void cp_async16(uint32_t dst, const void* src, int srcbytes) {
    asm volatile("cp.async.cg.shared.global [%0], [%1], 16, %2;"
                 :: "r"(dst), "l"(src), "r"(srcbytes) : "memory");
}
__device__ __forceinline__ void cp_commit() { asm volatile("cp.async.commit_group;" ::: "memory"); }
__device__ __forceinline__ void cp_wait0()  { asm volatile("cp.async.wait_group 0;" ::: "memory"); }

__device__ __forceinline__ void ldsm_x4(uint32_t& r0, uint32_t& r1, uint32_t& r2, uint32_t& r3,
                                        uint32_t addr) {
    asm volatile("ldmatrix.sync.aligned.m8n8.x4.shared.b16 {%0,%1,%2,%3}, [%4];"
                 : "=r"(r0), "=r"(r1), "=r"(r2), "=r"(r3) : "r"(addr));
}
__device__ __forceinline__ void mma16816(float* d, const uint32_t* a, const uint32_t* b) {
    asm volatile(
        "mma.sync.aligned.m16n8k16.row.col.f32.f16.f16.f32 "
        "{%0,%1,%2,%3}, {%4,%5,%6,%7}, {%8,%9}, {%0,%1,%2,%3};"
        : "+f"(d[0]), "+f"(d[1]), "+f"(d[2]), "+f"(d[3])
        : "r"(a[0]), "r"(a[1]), "r"(a[2]), "r"(a[3]), "r"(b[0]), "r"(b[1]));
}

// ------ prep: weight transposes (hi + lo*4096) + zero cnt + x->fp16 ------
__global__ void __launch_bounds__(256)
prep_kernel(const float* __restrict__ W10, const float* __restrict__ W20,
            const float* __restrict__ W11, const float* __restrict__ W21,
            const float* __restrict__ x,
            __half* __restrict__ wt, int* __restrict__ cnt,
            __half* __restrict__ x16) {
    int b = blockIdx.x;
    int tid = threadIdx.x;
    if (b >= 512 + ZB) {                 // x -> fp16 convert
        long i = ((long)(b - 512 - ZB) * 256 + tid) * 8;
        float4 v0 = *(const float4*)(x + i);
        float4 v1 = *(const float4*)(x + i + 4);
        __half2 h0 = __floats2half2_rn(v0.x, v0.y);
        __half2 h1 = __floats2half2_rn(v0.z, v0.w);
        __half2 h2 = __floats2half2_rn(v1.x, v1.y);
        __half2 h3 = __floats2half2_rn(v1.z, v1.w);
        *(uint4*)(x16 + i) = make_uint4(*(uint32_t*)&h0, *(uint32_t*)&h1,
                                        *(uint32_t*)&h2, *(uint32_t*)&h3);
        return;
    }
    if (b >= 512) {                      // zero cnt
        int i = (b - 512) * 256 + tid;
        if (i < NN) cnt[i] = 0;
        return;
    }
    int which = b >> 7;
    int i = ((b & 127) << 8) + tid;
    const float* W;
    int K, N;
    if (which == 0)      { W = W10; K = 128; N = 256; }
    else if (which == 1) { W = W20; K = 256; N = 128; }
    else if (which == 2) { W = W11; K = 128; N = 256; }
    else                 { W = W21; K = 256; N = 128; }
    int k = i / N, n = i % N;
    float a = W[i];
    __half h = __float2half_rn(a);
    __half l = __float2half_rn((a - __half2float(h)) * 4096.f);
    __half* thi = wt + (size_t)(2 * which) * 32768;
    __half* tlo = thi + 32768;
    thi[n * K + k] = h;
    tlo[n * K + k] = l;
}

// ---------------- bucket fill ----------------
__global__ void __launch_bounds__(256)
fill_kernel(const int* __restrict__ ei, const int* __restrict__ ea,
            int* __restrict__ cnt, uint32_t* __restrict__ payload, int E) {
    int e = blockIdx.x * 256 + threadIdx.x;
    if (e >= E) return;
    int src = ei[e];
    int dst = ei[E + e];
    int a0 = ea[2 * e];
    int a1 = ea[2 * e + 1];
    int pos = atomicAdd(&cnt[dst], 1);
    payload[((size_t)dst << 6) + pos] = (uint32_t)src | ((uint32_t)(a0 * 3 + a1) << 16);
}

// ---------------- gather (fp16 features) -> fp16 A ----------------
__global__ void __launch_bounds__(256)
gather_kernel(const __half* __restrict__ xh,
              const int* __restrict__ cnt, const uint32_t* __restrict__ payload,
              const float* __restrict__ ee1, const float* __restrict__ ee2,
              __half* __restrict__ A, int N) {
    __shared__ float combo[18 * 128];
    const int tid = threadIdx.x;
#pragma unroll
    for (int k = 0; k < 9; k++) {
        int idx = tid + k * 256;
        int c = idx >> 7, d = idx & 127;
        combo[idx] = ee1[(c / 3) * 128 + d] + ee2[(c % 3) * 128 + d];
    }
    __syncthreads();

    const int lane = tid & 31;
    const int n = blockIdx.x * 8 + (tid >> 5);
    if (n >= N) return;
    const int d4 = lane * 4;

    const uint32_t* pl = payload + ((size_t)n << 6);
    int deg = cnt[n];
    float4 acc = make_float4(0.f, 0.f, 0.f, 0.f);
    int i = 0;
    for (; i + 3 < deg; i += 4) {
        uint32_t p0 = pl[i], p1 = pl[i + 1], p2 = pl[i + 2], p3 = pl[i + 3];
        uint2 r0 = *(const uint2*)(xh + (size_t)(p0 & 0xFFFF) * 128 + d4);
        uint2 r1 = *(const uint2*)(xh + (size_t)(p1 & 0xFFFF) * 128 + d4);
        uint2 r2 = *(const uint2*)(xh + (size_t)(p2 & 0xFFFF) * 128 + d4);
        uint2 r3 = *(const uint2*)(xh + (size_t)(p3 & 0xFFFF) * 128 + d4);
        float4 c0 = *(const float4*)(combo + (p0 >> 16) * 128 + d4);
        float4 c1 = *(const float4*)(combo + (p1 >> 16) * 128 + d4);
        float4 c2 = *(const float4*)(combo + (p2 >> 16) * 128 + d4);
        float4 c3 = *(const float4*)(combo + (p3 >> 16) * 128 + d4);
        float2 a0 = __half22float2(*(__half2*)&r0.x), b0 = __half22float2(*(__half2*)&r0.y);
        float2 a1 = __half22float2(*(__half2*)&r1.x), b1 = __half22float2(*(__half2*)&r1.y);
        float2 a2 = __half22float2(*(__half2*)&r2.x), b2 = __half22float2(*(__half2*)&r2.y);
        float2 a3 = __half22float2(*(__half2*)&r3.x), b3 = __half22float2(*(__half2*)&r3.y);
        acc.x += (a0.x + c0.x) + (a1.x + c1.x) + (a2.x + c2.x) + (a3.x + c3.x);
        acc.y += (a0.y + c0.y) + (a1.y + c1.y) + (a2.y + c2.y) + (a3.y + c3.y);
        acc.z += (b0.x + c0.z) + (b1.x + c1.z) + (b2.x + c2.z) + (b3.x + c3.z);
        acc.w += (b0.y + c0.w) + (b1.y + c1.w) + (b2.y + c2.w) + (b3.y + c3.w);
    }
    for (; i < deg; i++) {
        uint32_t p0 = pl[i];
        uint2 r0 = *(const uint2*)(xh + (size_t)(p0 & 0xFFFF) * 128 + d4);
        float4 c0 = *(const float4*)(combo + (p0 >> 16) * 128 + d4);
        float2 a0 = __half22float2(*(__half2*)&r0.x), b0 = __half22float2(*(__half2*)&r0.y);
        acc.x += a0.x + c0.x;
        acc.y += a0.y + c0.y;
        acc.z += b0.x + c0.z;
        acc.w += b0.y + c0.w;
    }

    __half2 h01 = __floats2half2_rn(acc.x, acc.y);
    __half2 h23 = __floats2half2_rn(acc.z, acc.w);
    *(uint2*)(A + (size_t)n * 128 + d4) =
        make_uint2(*(uint32_t*)&h01, *(uint32_t*)&h23);
}

// =============== persistent GEMM 1: H = relu(A @ Wt1^T + b1) ================
#define SROWB 272
#define G1_B (256 * SROWB)
#define G1_AB (32 * SROWB)
#define G1_SMEM (2 * G1_B + 2 * G1_AB)   // 156672

__global__ void __launch_bounds__(512, 1)
gemm1p(const __half* __restrict__ A,
       const __half* __restrict__ Bhi, const __half* __restrict__ Blo,
       const float* __restrict__ bias,
       __half* __restrict__ H, int M) {
    extern __shared__ char smem[];
    const uint32_t sb = smem_u32(smem);
    const uint32_t sBhi = sb;
    const uint32_t sBlo = sb + G1_B;
    const uint32_t sA0  = sb + 2 * G1_B;

    const int tid  = threadIdx.x;
    const int lane = tid & 31;
    const int wid  = tid >> 5;
    const int wm   = (wid & 1) * 16;
    const int wn   = (wid >> 1) * 32;

#pragma unroll
    for (int i = 0; i < 8; i++) {
        int id = tid + i * 512;
        int row = id >> 4, off = (id & 15) * 16;
        uint32_t sdst = (uint32_t)(row * SROWB + off);
        cp_async16(sBhi + sdst, (const char*)(Bhi + (size_t)row * 128) + off, 16);
        cp_async16(sBlo + sdst, (const char*)(Blo + (size_t)row * 128) + off, 16);
    }

    int t = blockIdx.x;
    const int arow_ld = tid >> 4;
    const int aoff_ld = (tid & 15) * 16;
    if (t < NT32) {
        int grow = t * 32 + arow_ld;
        int asz = grow < M ? 16 : 0;
        uint32_t sdst = (uint32_t)(arow_ld * SROWB + aoff_ld);
        cp_async16(sA0 + sdst, (const char*)(A + (size_t)grow * 128) + aoff_ld, asz);
    }
    cp_commit();

    const uint32_t a_base = (uint32_t)((wm + (lane & 15)) * SROWB + ((lane >> 4) << 4));
    const int bg = lane >> 3, br = lane & 7;
    uint32_t b_base[2];
#pragma unroll
    for (int np = 0; np < 2; np++)
        b_base[np] = (uint32_t)((wn + np * 16 + ((bg & 2) ? 8 : 0) + br) * SROWB + ((bg & 1) << 4));

    int buf = 0;
    for (; t < NT32; t += GRIDP) {
        cp_wait0();
        __syncthreads();

        int tn = t + GRIDP;
        if (tn < NT32) {
            uint32_t base = sA0 + (buf ^ 1) * G1_AB;
            int grow = tn * 32 + arow_ld;
            int asz = grow < M ? 16 : 0;
            uint32_t sdst = (uint32_t)(arow_ld * SROWB + aoff_ld);
            cp_async16(base + sdst, (const char*)(A + (size_t)grow * 128) + aoff_ld, asz);
        }
        cp_commit();

        const uint32_t cA = sA0 + buf * G1_AB;
        float acc1[4][4], acc2[4][4];
#pragma unroll
        for (int j = 0; j < 4; j++)
#pragma unroll
            for (int k = 0; k < 4; k++) { acc1[j][k] = 0.f; acc2[j][k] = 0.f; }

#pragma unroll
        for (int kk = 0; kk < 8; kk++) {
            const uint32_t kb = (uint32_t)(kk * 32);
            uint32_t af[4];
            ldsm_x4(af[0], af[1], af[2], af[3], cA + a_base + kb);
            uint32_t bh[4][2], bl[4][2];
#pragma unroll
            for (int np = 0; np < 2; np++) {
                uint32_t r0, r1, r2, r3;
                ldsm_x4(r0, r1, r2, r3, sBhi + b_base[np] + kb);
                bh[np * 2][0] = r0; bh[np * 2][1] = r1;
                bh[np * 2 + 1][0] = r2; bh[np * 2 + 1][1] = r3;
                ldsm_x4(r0, r1, r2, r3, sBlo + b_base[np] + kb);
                bl[np * 2][0] = r0; bl[np * 2][1] = r1;
                bl[np * 2 + 1][0] = r2; bl[np * 2 + 1][1] = r3;
            }
#pragma unroll
            for (int nt = 0; nt < 4; nt++) {
                mma16816(acc1[nt], af, bh[nt]);
                mma16816(acc2[nt], af, bl[nt]);
            }
        }

        const int brow = t * 32;
#pragma unroll
        for (int nt = 0; nt < 4; nt++) {
            int gcol = wn + nt * 8 + (lane & 3) * 2;
            float b0 = bias[gcol], b1 = bias[gcol + 1];
#pragma unroll
            for (int hrow = 0; hrow < 2; hrow++) {
                int grow = brow + wm + (lane >> 2) + hrow * 8;
                if (grow < M) {
                    float o0 = fmaxf(fmaf(acc2[nt][hrow * 2 + 0], 1.f / 4096.f,
                                          acc1[nt][hrow * 2 + 0]) + b0, 0.f);
                    float o1 = fmaxf(fmaf(acc2[nt][hrow * 2 + 1], 1.f / 4096.f,
                                          acc1[nt][hrow * 2 + 1]) + b1, 0.f);
                    __half2 hp = __floats2half2_rn(o0, o1);
                    *(__half2*)(H + (size_t)grow * 256 + gcol) = hp;
                }
            }
        }
        buf ^= 1;
    }
}

// =============== persistent GEMM 2: C = act(H @ Wt2^T + b2) =================
// OUTHALF: write fp16 (layer-0 inter-layer features); else fp32 final out.
#define SROW2 528
#define G2_B (128 * SROW2)
#define G2_AB (32 * SROW2)
#define G2_SMEM (2 * G2_B + 2 * G2_AB)   // 168960

template <bool RELU, bool OUTHALF>
__global__ void __launch_bounds__(512, 1)
gemm2p(const __half* __restrict__ A,
       const __half* __restrict__ Bhi, const __half* __restrict__ Blo,
       const float* __restrict__ bias, void* __restrict__ Cv, int M) {
    extern __shared__ char smem[];
    const uint32_t sb = smem_u32(smem);
    const uint32_t sBhi = sb;
    const uint32_t sBlo = sb + G2_B;
    const uint32_t sA0  = sb + 2 * G2_B;

    const int tid  = threadIdx.x;
    const int lane = tid & 31;
    const int wid  = tid >> 5;
    const int wm   = (wid & 1) * 16;
    const int wn   = (wid >> 1) * 16;

#pragma unroll
    for (int i = 0; i < 8; i++) {
        int id = tid + i * 512;
        int row = id >> 5, off = (id & 31) * 16;
        uint32_t sdst = (uint32_t)(row * SROW2 + off);
        cp_async16(sBhi + sdst, (const char*)(Bhi + (size_t)row * 256) + off, 16);
        cp_async16(sBlo + sdst, (const char*)(Blo + (size_t)row * 256) + off, 16);
    }

    int t = blockIdx.x;
    if (t < NT32) {
#pragma unroll
        for (int i = 0; i < 2; i++) {
            int id2 = tid + i * 512;
            int row = id2 >> 5, off = (id2 & 31) * 16;
            int grow = t * 32 + row;
            int asz = grow < M ? 16 : 0;
            uint32_t sdst = (uint32_t)(row * SROW2 + off);
            cp_async16(sA0 + sdst, (const char*)(A + (size_t)grow * 256) + off, asz);
        }
    }
    cp_commit();

    const uint32_t a_base = (uint32_t)((wm + (lane & 15)) * SROW2 + ((lane >> 4) << 4));
    const int bg = lane >> 3, br = lane & 7;
    const uint32_t b_base = (uint32_t)((wn + ((bg & 2) ? 8 : 0) + br) * SROW2 + ((bg & 1) << 4));

    int buf = 0;
    for (; t < NT32; t += GRIDP) {
        cp_wait0();
        __syncthreads();

        int tn = t + GRIDP;
        if (tn < NT32) {
            uint32_t base = sA0 + (buf ^ 1) * G2_AB;
#pragma unroll
            for (int i = 0; i < 2; i++) {
                int id2 = tid + i * 512;
                int row = id2 >> 5, off = (id2 & 31) * 16;
                int grow = tn * 32 + row;
                int asz = grow < M ? 16 : 0;
                uint32_t sdst = (uint32_t)(row * SROW2 + off);
                cp_async16(base + sdst, (const char*)(A + (size_t)grow * 256) + off, asz);
            }
        }
        cp_commit();

        const uint32_t cA = sA0 + buf * G2_AB;
        float acc1[2][4], acc2[2][4];
#pragma unroll
        for (int j = 0; j < 2; j++)
#pragma unroll
            for (int k = 0; k < 4; k++) { acc1[j][k] = 0.f; acc2[j][k] = 0.f; }

#pragma unroll
        for (int kk = 0; kk < 16; kk++) {
            const uint32_t kb = (uint32_t)(kk * 32);
            uint32_t af[4];
            ldsm_x4(af[0], af[1], af[2], af[3], cA + a_base + kb);
            uint32_t bh[2][2], bl[2][2];
            {
                uint32_t r0, r1, r2, r3;
                ldsm_x4(r0, r1, r2, r3, sBhi + b_base + kb);
                bh[0][0] = r0; bh[0][1] = r1; bh[1][0] = r2; bh[1][1] = r3;
                ldsm_x4(r0, r1, r2, r3, sBlo + b_base + kb);
                bl[0][0] = r0; bl[0][1] = r1; bl[1][0] = r2; bl[1][1] = r3;
            }
#pragma unroll
            for (int nt = 0; nt < 2; nt++) {
                mma16816(acc1[nt], af, bh[nt]);
                mma16816(acc2[nt], af, bl[nt]);
            }
        }

        const int brow = t * 32;
#pragma unroll
        for (int nt = 0; nt < 2; nt++) {
            int gcol = wn + nt * 8 + (lane & 3) * 2;
            float b0 = bias[gcol], b1 = bias[gcol + 1];
#pragma unroll
            for (int hrow = 0; hrow < 2; hrow++) {
                int grow = brow + wm + (lane >> 2) + hrow * 8;
                if (grow < M) {
                    float o0 = fmaf(acc2[nt][hrow * 2 + 0], 1.f / 4096.f,
                                    acc1[nt][hrow * 2 + 0]) + b0;
                    float o1 = fmaf(acc2[nt][hrow * 2 + 1], 1.f / 4096.f,
                                    acc1[nt][hrow * 2 + 1]) + b1;
                    if (RELU) { o0 = fmaxf(o0, 0.f); o1 = fmaxf(o1, 0.f); }
                    if (OUTHALF) {
                        __half2 hp = __floats2half2_rn(o0, o1);
                        *(__half2*)((__half*)Cv + (size_t)grow * 128 + gcol) = hp;
                    } else {
                        *(float2*)((float*)Cv + (size_t)grow * 128 + gcol) = make_float2(o0, o1);
                    }
                }
            }
        }
        buf ^= 1;
    }
}

// ---------------- launch ----------------
extern "C" void kernel_launch(void* const* d_in, const int* in_sizes, int n_in,
                              void* d_out, int out_size) {
    const float* x     = (const float*)d_in[0];
    const int*   ei    = (const int*)d_in[1];
    const int*   ea    = (const int*)d_in[2];
    const float* ee1_0 = (const float*)d_in[3];
    const float* ee2_0 = (const float*)d_in[4];
    const float* W1_0  = (const float*)d_in[5];
    const float* b1_0  = (const float*)d_in[6];
    const float* W2_0  = (const float*)d_in[7];
    const float* b2_0  = (const float*)d_in[8];
    const float* ee1_1 = (const float*)d_in[9];
    const float* ee2_1 = (const float*)d_in[10];
    const float* W1_1  = (const float*)d_in[11];
    const float* b1_1  = (const float*)d_in[12];
    const float* W2_1  = (const float*)d_in[13];
    const float* b2_1  = (const float*)d_in[14];
    float* out = (float*)d_out;

    const int N = in_sizes[0] / DD;
    const int E = in_sizes[1] / 2;

    __half *x16, *A, *H, *Wt;
    int* cnt;
    uint32_t* payload;
    cudaGetSymbolAddress((void**)&x16, g_x16);
    cudaGetSymbolAddress((void**)&A, g_A);
    cudaGetSymbolAddress((void**)&H, g_H);
    cudaGetSymbolAddress((void**)&Wt, g_Wt);
    cudaGetSymbolAddress((void**)&cnt, g_cnt);
    cudaGetSymbolAddress((void**)&payload, g_payload);

    cudaFuncSetAttribute(gemm1p, cudaFuncAttributeMaxDynamicSharedMemorySize, G1_SMEM);
    cudaFuncSetAttribute(gemm2p<true, true>, cudaFuncAttributeMaxDynamicSharedMemorySize, G2_SMEM);
    cudaFuncSetAttribute(gemm2p<false, false>, cudaFuncAttributeMaxDynamicSharedMemorySize, G2_SMEM);

    const int ggrid = (N + 7) / 8;

    prep_kernel<<<512 + ZB + XCB, 256>>>(W1_0, W2_0, W1_1, W2_1, x, Wt, cnt, x16);
    fill_kernel<<<(E + 255) / 256, 256>>>(ei, ea, cnt, payload, E);

    // ============ layer 0 ============
    gather_kernel<<<ggrid, 256>>>(x16, cnt, payload, ee1_0, ee2_0, A, N);
    gemm1p<<<GRIDP, 512, G1_SMEM>>>(A, Wt + 0 * 32768, Wt + 1 * 32768, b1_0, H, N);
    gemm2p<true, true><<<GRIDP, 512, G2_SMEM>>>(H, Wt + 2 * 32768, Wt + 3 * 32768, b2_0, x16, N);

    // ============ layer 1 ============
    gather_kernel<<<ggrid, 256>>>(x16, cnt, payload, ee1_1, ee2_1, A, N);
    gemm1p<<<GRIDP, 512, G1_SMEM>>>(A, Wt + 4 * 32768, Wt + 5 * 32768, b1_1, H, N);
    gemm2p<false, false><<<GRIDP, 512, G2_SMEM>>>(H, Wt + 6 * 32768, Wt + 7 * 32768, b2_1, out, N);
}

// round 15
// speedup vs baseline: 2.5807x; 1.1452x over previous
#include <cuda_runtime.h>
#include <cuda_fp16.h>
#include <cstdint>

#define NN 50000
#define EE 800000
#define DD 128
#define BUCKET 64
#define GRIDP 296            // 2 persistent CTAs per SM
#define NT32 1563            // ceil(50000/32)
#define ZB 196               // ceil(NN/256)
#define XCB 3125             // (NN*128)/(256*8)

// ---------------- scratch (static device globals) ----------------
__device__ __half g_x16[(size_t)NN * DD];        // fp16 node features (x, then y0)
__device__ __half g_A[(size_t)NN * DD];          // fp16 aggr
__device__ __half g_H[(size_t)NN * 2 * DD];      // fp16 hidden
__device__ __half g_Wt[4][256 * 128];            // transposed fp16 weights
__device__ int g_cnt[NN];
__device__ uint32_t g_payload[(size_t)NN * BUCKET];

// ---------------- PTX helpers (base ISA only) ----------------
__device__ __forceinline__ uint32_t smem_u32(const void* p) {
    uint32_t a;
    asm("{ .reg .u64 t; cvta.to.shared.u64 t, %1; cvt.u32.u64 %0, t; }" : "=r"(a) : "l"(p));
    return a;
}
__device__ __forceinline__ void cp_async16(uint32_t dst, const void* src, int srcbytes) {
    asm volatile("cp.async.cg.shared.global [%0], [%1], 16, %2;"
                 :: "r"(dst), "l"(src), "r"(srcbytes) : "memory");
}
__device__ __forceinline__ void cp_commit() { asm volatile("cp.async.commit_group;" ::: "memory"); }
__device__ __forceinline__ void cp_wait0()  { asm volatile("cp.async.wait_group 0;" ::: "memory"); }

__device__ __forceinline__ void ldsm_x4(uint32_t& r0, uint32_t& r1, uint32_t& r2, uint32_t& r3,
                                        uint32_t addr) {
    asm volatile("ldmatrix.sync.aligned.m8n8.x4.shared.b16 {%0,%1,%2,%3}, [%4];"
                 : "=r"(r0), "=r"(r1), "=r"(r2), "=r"(r3) : "r"(addr));
}
__device__ __forceinline__ void mma16816(float* d, const uint32_t* a, const uint32_t* b) {
    asm volatile(
        "mma.sync.aligned.m16n8k16.row.col.f32.f16.f16.f32 "
        "{%0,%1,%2,%3}, {%4,%5,%6,%7}, {%8,%9}, {%0,%1,%2,%3};"
        : "+f"(d[0]), "+f"(d[1]), "+f"(d[2]), "+f"(d[3])
        : "r"(a[0]), "r"(a[1]), "r"(a[2]), "r"(a[3]), "r"(b[0]), "r"(b[1]));
}

// ------ prep: weight transposes (fp16) + zero cnt + x->fp16 ------
__global__ void __launch_bounds__(256)
prep_kernel(const float* __restrict__ W10, const float* __restrict__ W20,
            const float* __restrict__ W11, const float* __restrict__ W21,
            const float* __restrict__ x,
            __half* __restrict__ wt, int* __restrict__ cnt,
            __half* __restrict__ x16) {
    int b = blockIdx.x;
    int tid = threadIdx.x;
    if (b >= 512 + ZB) {                 // x -> fp16 convert
        long i = ((long)(b - 512 - ZB) * 256 + tid) * 8;
        float4 v0 = *(const float4*)(x + i);
        float4 v1 = *(const float4*)(x + i + 4);
        __half2 h0 = __floats2half2_rn(v0.x, v0.y);
        __half2 h1 = __floats2half2_rn(v0.z, v0.w);
        __half2 h2 = __floats2half2_rn(v1.x, v1.y);
        __half2 h3 = __floats2half2_rn(v1.z, v1.w);
        *(uint4*)(x16 + i) = make_uint4(*(uint32_t*)&h0, *(uint32_t*)&h1,
                                        *(uint32_t*)&h2, *(uint32_t*)&h3);
        return;
    }
    if (b >= 512) {                      // zero cnt
        int i = (b - 512) * 256 + tid;
        if (i < NN) cnt[i] = 0;
        return;
    }
    int which = b >> 7;
    int i = ((b & 127) << 8) + tid;
    const float* W;
    int K, N;
    if (which == 0)      { W = W10; K = 128; N = 256; }
    else if (which == 1) { W = W20; K = 256; N = 128; }
    else if (which == 2) { W = W11; K = 128; N = 256; }
    else                 { W = W21; K = 256; N = 128; }
    int k = i / N, n = i % N;
    wt[(size_t)which * 32768 + n * K + k] = __float2half_rn(W[i]);
}

// ---------------- bucket fill ----------------
__global__ void __launch_bounds__(256)
fill_kernel(const int* __restrict__ ei, const int* __restrict__ ea,
            int* __restrict__ cnt, uint32_t* __restrict__ payload, int E) {
    int e = blockIdx.x * 256 + threadIdx.x;
    if (e >= E) return;
    int src = ei[e];
    int dst = ei[E + e];
    int a0 = ea[2 * e];
    int a1 = ea[2 * e + 1];
    int pos = atomicAdd(&cnt[dst], 1);
    payload[((size_t)dst << 6) + pos] = (uint32_t)src | ((uint32_t)(a0 * 3 + a1) << 16);
}

// ---------------- gather (fp16 features) -> fp16 A ----------------
__global__ void __launch_bounds__(256)
gather_kernel(const __half* __restrict__ xh,
              const int* __restrict__ cnt, const uint32_t* __restrict__ payload,
              const float* __restrict__ ee1, const float* __restrict__ ee2,
              __half* __restrict__ A, int N) {
    __shared__ float combo[18 * 128];
    const int tid = threadIdx.x;
#pragma unroll
    for (int k = 0; k < 9; k++) {
        int idx = tid + k * 256;
        int c = idx >> 7, d = idx & 127;
        combo[idx] = ee1[(c / 3) * 128 + d] + ee2[(c % 3) * 128 + d];
    }
    __syncthreads();

    const int lane = tid & 31;
    const int n = blockIdx.x * 8 + (tid >> 5);
    if (n >= N) return;
    const int d4 = lane * 4;

    const uint32_t* pl = payload + ((size_t)n << 6);
    int deg = cnt[n];
    float4 acc = make_float4(0.f, 0.f, 0.f, 0.f);
    int i = 0;
    for (; i + 3 < deg; i += 4) {
        uint32_t p0 = pl[i], p1 = pl[i + 1], p2 = pl[i + 2], p3 = pl[i + 3];
        uint2 r0 = *(const uint2*)(xh + (size_t)(p0 & 0xFFFF) * 128 + d4);
        uint2 r1 = *(const uint2*)(xh + (size_t)(p1 & 0xFFFF) * 128 + d4);
        uint2 r2 = *(const uint2*)(xh + (size_t)(p2 & 0xFFFF) * 128 + d4);
        uint2 r3 = *(const uint2*)(xh + (size_t)(p3 & 0xFFFF) * 128 + d4);
        float4 c0 = *(const float4*)(combo + (p0 >> 16) * 128 + d4);
        float4 c1 = *(const float4*)(combo + (p1 >> 16) * 128 + d4);
        float4 c2 = *(const float4*)(combo + (p2 >> 16) * 128 + d4);
        float4 c3 = *(const float4*)(combo + (p3 >> 16) * 128 + d4);
        float2 a0 = __half22float2(*(__half2*)&r0.x), b0 = __half22float2(*(__half2*)&r0.y);
        float2 a1 = __half22float2(*(__half2*)&r1.x), b1 = __half22float2(*(__half2*)&r1.y);
        float2 a2 = __half22float2(*(__half2*)&r2.x), b2 = __half22float2(*(__half2*)&r2.y);
        float2 a3 = __half22float2(*(__half2*)&r3.x), b3 = __half22float2(*(__half2*)&r3.y);
        acc.x += (a0.x + c0.x) + (a1.x + c1.x) + (a2.x + c2.x) + (a3.x + c3.x);
        acc.y += (a0.y + c0.y) + (a1.y + c1.y) + (a2.y + c2.y) + (a3.y + c3.y);
        acc.z += (b0.x + c0.z) + (b1.x + c1.z) + (b2.x + c2.z) + (b3.x + c3.z);
        acc.w += (b0.y + c0.w) + (b1.y + c1.w) + (b2.y + c2.w) + (b3.y + c3.w);
    }
    for (; i < deg; i++) {
        uint32_t p0 = pl[i];
        uint2 r0 = *(const uint2*)(xh + (size_t)(p0 & 0xFFFF) * 128 + d4);
        float4 c0 = *(const float4*)(combo + (p0 >> 16) * 128 + d4);
        float2 a0 = __half22float2(*(__half2*)&r0.x), b0 = __half22float2(*(__half2*)&r0.y);
        acc.x += a0.x + c0.x;
        acc.y += a0.y + c0.y;
        acc.z += b0.x + c0.z;
        acc.w += b0.y + c0.w;
    }

    __half2 h01 = __floats2half2_rn(acc.x, acc.y);
    __half2 h23 = __floats2half2_rn(acc.z, acc.w);
    *(uint2*)(A + (size_t)n * 128 + d4) =
        make_uint2(*(uint32_t*)&h01, *(uint32_t*)&h23);
}

// =============== persistent GEMM 1: H = relu(A @ Wt1^T + b1) ================
// Single-pass fp16. 512 threads, warp tile 16x32. 2 CTAs/SM.
#define SROWB 272
#define G1_B (256 * SROWB)            // 69632
#define G1_AB (32 * SROWB)            // 8704 per buffer
#define G1_SMEM (G1_B + 2 * G1_AB)    // 87040

__global__ void __launch_bounds__(512, 2)
gemm1p(const __half* __restrict__ A, const __half* __restrict__ B,
       const float* __restrict__ bias, __half* __restrict__ H, int M) {
    extern __shared__ char smem[];
    const uint32_t sb = smem_u32(smem);
    const uint32_t sB  = sb;
    const uint32_t sA0 = sb + G1_B;

    const int tid  = threadIdx.x;
    const int lane = tid & 31;
    const int wid  = tid >> 5;
    const int wm   = (wid & 1) * 16;
    const int wn   = (wid >> 1) * 32;

    // ---- load resident B: 256 rows x 256B ----
#pragma unroll
    for (int i = 0; i < 8; i++) {
        int id = tid + i * 512;
        int row = id >> 4, off = (id & 15) * 16;
        cp_async16(sB + (uint32_t)(row * SROWB + off),
                   (const char*)(B + (size_t)row * 128) + off, 16);
    }

    int t = blockIdx.x;
    const int arow_ld = tid >> 4;
    const int aoff_ld = (tid & 15) * 16;
    if (t < NT32) {
        int grow = t * 32 + arow_ld;
        int asz = grow < M ? 16 : 0;
        cp_async16(sA0 + (uint32_t)(arow_ld * SROWB + aoff_ld),
                   (const char*)(A + (size_t)grow * 128) + aoff_ld, asz);
    }
    cp_commit();

    const uint32_t a_base = (uint32_t)((wm + (lane & 15)) * SROWB + ((lane >> 4) << 4));
    const int bg = lane >> 3, br = lane & 7;
    uint32_t b_base[2];
#pragma unroll
    for (int np = 0; np < 2; np++)
        b_base[np] = (uint32_t)((wn + np * 16 + ((bg & 2) ? 8 : 0) + br) * SROWB + ((bg & 1) << 4));

    int buf = 0;
    for (; t < NT32; t += GRIDP) {
        cp_wait0();
        __syncthreads();

        int tn = t + GRIDP;
        if (tn < NT32) {
            uint32_t base = sA0 + (buf ^ 1) * G1_AB;
            int grow = tn * 32 + arow_ld;
            int asz = grow < M ? 16 : 0;
            cp_async16(base + (uint32_t)(arow_ld * SROWB + aoff_ld),
                       (const char*)(A + (size_t)grow * 128) + aoff_ld, asz);
        }
        cp_commit();

        const uint32_t cA = sA0 + buf * G1_AB;
        float acc[4][4];
#pragma unroll
        for (int j = 0; j < 4; j++)
#pragma unroll
            for (int k = 0; k < 4; k++) acc[j][k] = 0.f;

#pragma unroll
        for (int kk = 0; kk < 8; kk++) {
            const uint32_t kb = (uint32_t)(kk * 32);
            uint32_t af[4];
            ldsm_x4(af[0], af[1], af[2], af[3], cA + a_base + kb);
            uint32_t bf[4][2];
#pragma unroll
            for (int np = 0; np < 2; np++) {
                uint32_t r0, r1, r2, r3;
                ldsm_x4(r0, r1, r2, r3, sB + b_base[np] + kb);
                bf[np * 2][0] = r0; bf[np * 2][1] = r1;
                bf[np * 2 + 1][0] = r2; bf[np * 2 + 1][1] = r3;
            }
#pragma unroll
            for (int nt = 0; nt < 4; nt++)
                mma16816(acc[nt], af, bf[nt]);
        }

        const int brow = t * 32;
#pragma unroll
        for (int nt = 0; nt < 4; nt++) {
            int gcol = wn + nt * 8 + (lane & 3) * 2;
            float b0 = bias[gcol], b1 = bias[gcol + 1];
#pragma unroll
            for (int hrow = 0; hrow < 2; hrow++) {
                int grow = brow + wm + (lane >> 2) + hrow * 8;
                if (grow < M) {
                    float o0 = fmaxf(acc[nt][hrow * 2 + 0] + b0, 0.f);
                    float o1 = fmaxf(acc[nt][hrow * 2 + 1] + b1, 0.f);
                    __half2 hp = __floats2half2_rn(o0, o1);
                    *(__half2*)(H + (size_t)grow * 256 + gcol) = hp;
                }
            }
        }
        buf ^= 1;
    }
}

// =============== persistent GEMM 2: C = act(H @ Wt2^T + b2) =================
// Single-pass fp16. 512 threads, warp tile 16x16, K=256. 2 CTAs/SM.
#define SROW2 528
#define G2_B (128 * SROW2)            // 67584
#define G2_AB (32 * SROW2)            // 16896 per buffer
#define G2_SMEM (G2_B + 2 * G2_AB)    // 101376

template <bool RELU, bool OUTHALF>
__global__ void __launch_bounds__(512, 2)
gemm2p(const __half* __restrict__ A, const __half* __restrict__ B,
       const float* __restrict__ bias, void* __restrict__ Cv, int M) {
    extern __shared__ char smem[];
    const uint32_t sb = smem_u32(smem);
    const uint32_t sB  = sb;
    const uint32_t sA0 = sb + G2_B;

    const int tid  = threadIdx.x;
    const int lane = tid & 31;
    const int wid  = tid >> 5;
    const int wm   = (wid & 1) * 16;
    const int wn   = (wid >> 1) * 16;

    // ---- load resident B: 128 rows x 512B ----
#pragma unroll
    for (int i = 0; i < 8; i++) {
        int id = tid + i * 512;
        int row = id >> 5, off = (id & 31) * 16;
        cp_async16(sB + (uint32_t)(row * SROW2 + off),
                   (const char*)(B + (size_t)row * 256) + off, 16);
    }

    int t = blockIdx.x;
    if (t < NT32) {
#pragma unroll
        for (int i = 0; i < 2; i++) {
            int id2 = tid + i * 512;
            int row = id2 >> 5, off = (id2 & 31) * 16;
            int grow = t * 32 + row;
            int asz = grow < M ? 16 : 0;
            cp_async16(sA0 + (uint32_t)(row * SROW2 + off),
                       (const char*)(A + (size_t)grow * 256) + off, asz);
        }
    }
    cp_commit();

    const uint32_t a_base = (uint32_t)((wm + (lane & 15)) * SROW2 + ((lane >> 4) << 4));
    const int bg = lane >> 3, br = lane & 7;
    const uint32_t b_base = (uint32_t)((wn + ((bg & 2) ? 8 : 0) + br) * SROW2 + ((bg & 1) << 4));

    int buf = 0;
    for (; t < NT32; t += GRIDP) {
        cp_wait0();
        __syncthreads();

        int tn = t + GRIDP;
        if (tn < NT32) {
            uint32_t base = sA0 + (buf ^ 1) * G2_AB;
#pragma unroll
            for (int i = 0; i < 2; i++) {
                int id2 = tid + i * 512;
                int row = id2 >> 5, off = (id2 & 31) * 16;
                int grow = tn * 32 + row;
                int asz = grow < M ? 16 : 0;
                cp_async16(base + (uint32_t)(row * SROW2 + off),
                           (const char*)(A + (size_t)grow * 256) + off, asz);
            }
        }
        cp_commit();

        const uint32_t cA = sA0 + buf * G2_AB;
        float acc[2][4];
#pragma unroll
        for (int j = 0; j < 2; j++)
#pragma unroll
            for (int k = 0; k < 4; k++) acc[j][k] = 0.f;

#pragma unroll
        for (int kk = 0; kk < 16; kk++) {
            const uint32_t kb = (uint32_t)(kk * 32);
            uint32_t af[4];
            ldsm_x4(af[0], af[1], af[2], af[3], cA + a_base + kb);
            uint32_t bf[2][2];
            {
                uint32_t r0, r1, r2, r3;
                ldsm_x4(r0, r1, r2, r3, sB + b_base + kb);
                bf[0][0] = r0; bf[0][1] = r1; bf[1][0] = r2; bf[1][1] = r3;
            }
#pragma unroll
            for (int nt = 0; nt < 2; nt++)
                mma16816(acc[nt], af, bf[nt]);
        }

        const int brow = t * 32;
#pragma unroll
        for (int nt = 0; nt < 2; nt++) {
            int gcol = wn + nt * 8 + (lane & 3) * 2;
            float b0 = bias[gcol], b1 = bias[gcol + 1];
#pragma unroll
            for (int hrow = 0; hrow < 2; hrow++) {
                int grow = brow + wm + (lane >> 2) + hrow * 8;
                if (grow < M) {
                    float o0 = acc[nt][hrow * 2 + 0] + b0;
                    float o1 = acc[nt][hrow * 2 + 1] + b1;
                    if (RELU) { o0 = fmaxf(o0, 0.f); o1 = fmaxf(o1, 0.f); }
                    if (OUTHALF) {
                        __half2 hp = __floats2half2_rn(o0, o1);
                        *(__half2*)((__half*)Cv + (size_t)grow * 128 + gcol) = hp;
                    } else {
                        *(float2*)((float*)Cv + (size_t)grow * 128 + gcol) = make_float2(o0, o1);
                    }
                }
            }
        }
        buf ^= 1;
    }
}

// ---------------- launch ----------------
extern "C" void kernel_launch(void* const* d_in, const int* in_sizes, int n_in,
                              void* d_out, int out_size) {
    const float* x     = (const float*)d_in[0];
    const int*   ei    = (const int*)d_in[1];
    const int*   ea    = (const int*)d_in[2];
    const float* ee1_0 = (const float*)d_in[3];
    const float* ee2_0 = (const float*)d_in[4];
    const float* W1_0  = (const float*)d_in[5];
    const float* b1_0  = (const float*)d_in[6];
    const float* W2_0  = (const float*)d_in[7];
    const float* b2_0  = (const float*)d_in[8];
    const float* ee1_1 = (const float*)d_in[9];
    const float* ee2_1 = (const float*)d_in[10];
    const float* W1_1  = (const float*)d_in[11];
    const float* b1_1  = (const float*)d_in[12];
    const float* W2_1  = (const float*)d_in[13];
    const float* b2_1  = (const float*)d_in[14];
    float* out = (float*)d_out;

    const int N = in_sizes[0] / DD;
    const int E = in_sizes[1] / 2;

    __half *x16, *A, *H, *Wt;
    int* cnt;
    uint32_t* payload;
    cudaGetSymbolAddress((void**)&x16, g_x16);
    cudaGetSymbolAddress((void**)&A, g_A);
    cudaGetSymbolAddress((void**)&H, g_H);
    cudaGetSymbolAddress((void**)&Wt, g_Wt);
    cudaGetSymbolAddress((void**)&cnt, g_cnt);
    cudaGetSymbolAddress((void**)&payload, g_payload);

    cudaFuncSetAttribute(gemm1p, cudaFuncAttributeMaxDynamicSharedMemorySize, G1_SMEM);
    cudaFuncSetAttribute(gemm2p<true, true>, cudaFuncAttributeMaxDynamicSharedMemorySize, G2_SMEM);
    cudaFuncSetAttribute(gemm2p<false, false>, cudaFuncAttributeMaxDynamicSharedMemorySize, G2_SMEM);

    const int ggrid = (N + 7) / 8;

    prep_kernel<<<512 + ZB + XCB, 256>>>(W1_0, W2_0, W1_1, W2_1, x, Wt, cnt, x16);
    fill_kernel<<<(E + 255) / 256, 256>>>(ei, ea, cnt, payload, E);

    // ============ layer 0 ============
    gather_kernel<<<ggrid, 256>>>(x16, cnt, payload, ee1_0, ee2_0, A, N);
    gemm1p<<<GRIDP, 512, G1_SMEM>>>(A, Wt + 0 * 32768, b1_0, H, N);
    gemm2p<true, true><<<GRIDP, 512, G2_SMEM>>>(H, Wt + 1 * 32768, b2_0, x16, N);

    // ============ layer 1 ============
    gather_kernel<<<ggrid, 256>>>(x16, cnt, payload, ee1_1, ee2_1, A, N);
    gemm1p<<<GRIDP, 512, G1_SMEM>>>(A, Wt + 2 * 32768, b1_1, H, N);
    gemm2p<false, false><<<GRIDP, 512, G2_SMEM>>>(H, Wt + 3 * 32768, b2_1, out, N);
}

// round 16
// speedup vs baseline: 2.5917x; 1.0043x over previous
#include <cuda_runtime.h>
#include <cuda_fp16.h>
#include <cstdint>

#define NN 50000
#define EE 800000
#define DD 128
#define BUCKET 64
#define GRIDP 296            // 2 persistent CTAs per SM
#define NT32 1563            // ceil(50000/32)
#define NT64 782             // ceil(50000/64)
#define ZB 196               // ceil(NN/256)
#define XCB 3125             // (NN*128)/(256*8)

// ---------------- scratch (static device globals) ----------------
__device__ __half g_x16[(size_t)NN * DD];        // fp16 node features (x, then y0)
__device__ __half g_A[(size_t)NN * DD];          // fp16 aggr
__device__ __half g_H[(size_t)NN * 2 * DD];      // fp16 hidden
__device__ __half g_Wt[4][256 * 128];            // transposed fp16 weights
__device__ int g_cnt[NN];
__device__ uint32_t g_payload[(size_t)NN * BUCKET];

// ---------------- PTX helpers (base ISA only) ----------------
__device__ __forceinline__ uint32_t smem_u32(const void* p) {
    uint32_t a;
    asm("{ .reg .u64 t; cvta.to.shared.u64 t, %1; cvt.u32.u64 %0, t; }" : "=r"(a) : "l"(p));
    return a;
}
__device__ __forceinline__ void cp_async16(uint32_t dst, const void* src, int srcbytes) {
    asm volatile("cp.async.cg.shared.global [%0], [%1], 16, %2;"
                 :: "r"(dst), "l"(src), "r"(srcbytes) : "memory");
}
__device__ __forceinline__ void cp_commit() { asm volatile("cp.async.commit_group;" ::: "memory"); }
__device__ __forceinline__ void cp_wait0()  { asm volatile("cp.async.wait_group 0;" ::: "memory"); }

__device__ __forceinline__ void ldsm_x4(uint32_t& r0, uint32_t& r1, uint32_t& r2, uint32_t& r3,
                                        uint32_t addr) {
    asm volatile("ldmatrix.sync.aligned.m8n8.x4.shared.b16 {%0,%1,%2,%3}, [%4];"
                 : "=r"(r0), "=r"(r1), "=r"(r2), "=r"(r3) : "r"(addr));
}
__device__ __forceinline__ void mma16816(float* d, const uint32_t* a, const uint32_t* b) {
    asm volatile(
        "mma.sync.aligned.m16n8k16.row.col.f32.f16.f16.f32 "
        "{%0,%1,%2,%3}, {%4,%5,%6,%7}, {%8,%9}, {%0,%1,%2,%3};"
        : "+f"(d[0]), "+f"(d[1]), "+f"(d[2]), "+f"(d[3])
        : "r"(a[0]), "r"(a[1]), "r"(a[2]), "r"(a[3]), "r"(b[0]), "r"(b[1]));
}

// ------ prep: weight transposes (fp16) + zero cnt + x->fp16 ------
__global__ void __launch_bounds__(256)
prep_kernel(const float* __restrict__ W10, const float* __restrict__ W20,
            const float* __restrict__ W11, const float* __restrict__ W21,
            const float* __restrict__ x,
            __half* __restrict__ wt, int* __restrict__ cnt,
            __half* __restrict__ x16) {
    int b = blockIdx.x;
    int tid = threadIdx.x;
    if (b >= 512 + ZB) {                 // x -> fp16 convert
        long i = ((long)(b - 512 - ZB) * 256 + tid) * 8;
        float4 v0 = *(const float4*)(x + i);
        float4 v1 = *(const float4*)(x + i + 4);
        __half2 h0 = __floats2half2_rn(v0.x, v0.y);
        __half2 h1 = __floats2half2_rn(v0.z, v0.w);
        __half2 h2 = __floats2half2_rn(v1.x, v1.y);
        __half2 h3 = __floats2half2_rn(v1.z, v1.w);
        *(uint4*)(x16 + i) = make_uint4(*(uint32_t*)&h0, *(uint32_t*)&h1,
                                        *(uint32_t*)&h2, *(uint32_t*)&h3);
        return;
    }
    if (b >= 512) {                      // zero cnt
        int i = (b - 512) * 256 + tid;
        if (i < NN) cnt[i] = 0;
        return;
    }
    int which = b >> 7;
    int i = ((b & 127) << 8) + tid;
    const float* W;
    int K, N;
    if (which == 0)      { W = W10; K = 128; N = 256; }
    else if (which == 1) { W = W20; K = 256; N = 128; }
    else if (which == 2) { W = W11; K = 128; N = 256; }
    else                 { W = W21; K = 256; N = 128; }
    int k = i / N, n = i % N;
    wt[(size_t)which * 32768 + n * K + k] = __float2half_rn(W[i]);
}

// ---------------- bucket fill ----------------
__global__ void __launch_bounds__(256)
fill_kernel(const int* __restrict__ ei, const int* __restrict__ ea,
            int* __restrict__ cnt, uint32_t* __restrict__ payload, int E) {
    int e = blockIdx.x * 256 + threadIdx.x;
    if (e >= E) return;
    int src = ei[e];
    int dst = ei[E + e];
    int a0 = ea[2 * e];
    int a1 = ea[2 * e + 1];
    int pos = atomicAdd(&cnt[dst], 1);
    payload[((size_t)dst << 6) + pos] = (uint32_t)src | ((uint32_t)(a0 * 3 + a1) << 16);
}

// ---------------- gather (fp16 features) -> fp16 A ----------------
__global__ void __launch_bounds__(256)
gather_kernel(const __half* __restrict__ xh,
              const int* __restrict__ cnt, const uint32_t* __restrict__ payload,
              const float* __restrict__ ee1, const float* __restrict__ ee2,
              __half* __restrict__ A, int N) {
    __shared__ float combo[18 * 128];
    const int tid = threadIdx.x;
#pragma unroll
    for (int k = 0; k < 9; k++) {
        int idx = tid + k * 256;
        int c = idx >> 7, d = idx & 127;
        combo[idx] = ee1[(c / 3) * 128 + d] + ee2[(c % 3) * 128 + d];
    }
    __syncthreads();

    const int lane = tid & 31;
    const int n = blockIdx.x * 8 + (tid >> 5);
    if (n >= N) return;
    const int d4 = lane * 4;

    const uint32_t* pl = payload + ((size_t)n << 6);
    int deg = cnt[n];
    float4 acc = make_float4(0.f, 0.f, 0.f, 0.f);
    int i = 0;
    for (; i + 3 < deg; i += 4) {
        uint32_t p0 = pl[i], p1 = pl[i + 1], p2 = pl[i + 2], p3 = pl[i + 3];
        uint2 r0 = *(const uint2*)(xh + (size_t)(p0 & 0xFFFF) * 128 + d4);
        uint2 r1 = *(const uint2*)(xh + (size_t)(p1 & 0xFFFF) * 128 + d4);
        uint2 r2 = *(const uint2*)(xh + (size_t)(p2 & 0xFFFF) * 128 + d4);
        uint2 r3 = *(const uint2*)(xh + (size_t)(p3 & 0xFFFF) * 128 + d4);
        float4 c0 = *(const float4*)(combo + (p0 >> 16) * 128 + d4);
        float4 c1 = *(const float4*)(combo + (p1 >> 16) * 128 + d4);
        float4 c2 = *(const float4*)(combo + (p2 >> 16) * 128 + d4);
        float4 c3 = *(const float4*)(combo + (p3 >> 16) * 128 + d4);
        float2 a0 = __half22float2(*(__half2*)&r0.x), b0 = __half22float2(*(__half2*)&r0.y);
        float2 a1 = __half22float2(*(__half2*)&r1.x), b1 = __half22float2(*(__half2*)&r1.y);
        float2 a2 = __half22float2(*(__half2*)&r2.x), b2 = __half22float2(*(__half2*)&r2.y);
        float2 a3 = __half22float2(*(__half2*)&r3.x), b3 = __half22float2(*(__half2*)&r3.y);
        acc.x += (a0.x + c0.x) + (a1.x + c1.x) + (a2.x + c2.x) + (a3.x + c3.x);
        acc.y += (a0.y + c0.y) + (a1.y + c1.y) + (a2.y + c2.y) + (a3.y + c3.y);
        acc.z += (b0.x + c0.z) + (b1.x + c1.z) + (b2.x + c2.z) + (b3.x + c3.z);
        acc.w += (b0.y + c0.w) + (b1.y + c1.w) + (b2.y + c2.w) + (b3.y + c3.w);
    }
    for (; i < deg; i++) {
        uint32_t p0 = pl[i];
        uint2 r0 = *(const uint2*)(xh + (size_t)(p0 & 0xFFFF) * 128 + d4);
        float4 c0 = *(const float4*)(combo + (p0 >> 16) * 128 + d4);
        float2 a0 = __half22float2(*(__half2*)&r0.x), b0 = __half22float2(*(__half2*)&r0.y);
        acc.x += a0.x + c0.x;
        acc.y += a0.y + c0.y;
        acc.z += b0.x + c0.z;
        acc.w += b0.y + c0.w;
    }

    __half2 h01 = __floats2half2_rn(acc.x, acc.y);
    __half2 h23 = __floats2half2_rn(acc.z, acc.w);
    *(uint2*)(A + (size_t)n * 128 + d4) =
        make_uint2(*(uint32_t*)&h01, *(uint32_t*)&h23);
}

// =============== persistent GEMM 1: H = relu(A @ Wt1^T + b1) ================
// Single-pass fp16. 512 threads = 16 warps, M-tile 64, warp tile 16x64
// (wm=(wid&3)*16, wn=(wid>>2)*64). 2 CTAs/SM.
#define SROWB 272
#define G1_B (256 * SROWB)            // 69632
#define G1_AB (64 * SROWB)            // 17408 per buffer
#define G1_SMEM (G1_B + 2 * G1_AB)    // 104448

__global__ void __launch_bounds__(512, 2)
gemm1p(const __half* __restrict__ A, const __half* __restrict__ B,
       const float* __restrict__ bias, __half* __restrict__ H, int M) {
    extern __shared__ char smem[];
    const uint32_t sb = smem_u32(smem);
    const uint32_t sB  = sb;
    const uint32_t sA0 = sb + G1_B;

    const int tid  = threadIdx.x;
    const int lane = tid & 31;
    const int wid  = tid >> 5;
    const int wm   = (wid & 3) * 16;
    const int wn   = (wid >> 2) * 64;

    // ---- load resident B: 256 rows x 256B ----
#pragma unroll
    for (int i = 0; i < 8; i++) {
        int id = tid + i * 512;
        int row = id >> 4, off = (id & 15) * 16;
        cp_async16(sB + (uint32_t)(row * SROWB + off),
                   (const char*)(B + (size_t)row * 128) + off, 16);
    }

    // ---- issue first A tile: 64 rows x 256B ----
    int t = blockIdx.x;
    if (t < NT64) {
#pragma unroll
        for (int i = 0; i < 2; i++) {
            int id = tid + i * 512;
            int row = id >> 4, off = (id & 15) * 16;
            int grow = t * 64 + row;
            int asz = grow < M ? 16 : 0;
            cp_async16(sA0 + (uint32_t)(row * SROWB + off),
                       (const char*)(A + (size_t)grow * 128) + off, asz);
        }
    }
    cp_commit();

    const uint32_t a_base = (uint32_t)((wm + (lane & 15)) * SROWB + ((lane >> 4) << 4));
    const int bg = lane >> 3, br = lane & 7;
    uint32_t b_base[4];
#pragma unroll
    for (int np = 0; np < 4; np++)
        b_base[np] = (uint32_t)((wn + np * 16 + ((bg & 2) ? 8 : 0) + br) * SROWB + ((bg & 1) << 4));

    int buf = 0;
    for (; t < NT64; t += GRIDP) {
        cp_wait0();
        __syncthreads();

        int tn = t + GRIDP;
        if (tn < NT64) {
            uint32_t base = sA0 + (buf ^ 1) * G1_AB;
#pragma unroll
            for (int i = 0; i < 2; i++) {
                int id = tid + i * 512;
                int row = id >> 4, off = (id & 15) * 16;
                int grow = tn * 64 + row;
                int asz = grow < M ? 16 : 0;
                cp_async16(base + (uint32_t)(row * SROWB + off),
                           (const char*)(A + (size_t)grow * 128) + off, asz);
            }
        }
        cp_commit();

        const uint32_t cA = sA0 + buf * G1_AB;
        float acc[8][4];
#pragma unroll
        for (int j = 0; j < 8; j++)
#pragma unroll
            for (int k = 0; k < 4; k++) acc[j][k] = 0.f;

#pragma unroll
        for (int kk = 0; kk < 8; kk++) {
            const uint32_t kb = (uint32_t)(kk * 32);
            uint32_t af[4];
            ldsm_x4(af[0], af[1], af[2], af[3], cA + a_base + kb);
            uint32_t bf[8][2];
#pragma unroll
            for (int np = 0; np < 4; np++) {
                uint32_t r0, r1, r2, r3;
                ldsm_x4(r0, r1, r2, r3, sB + b_base[np] + kb);
                bf[np * 2][0] = r0; bf[np * 2][1] = r1;
                bf[np * 2 + 1][0] = r2; bf[np * 2 + 1][1] = r3;
            }
#pragma unroll
            for (int nt = 0; nt < 8; nt++)
                mma16816(acc[nt], af, bf[nt]);
        }

        const int brow = t * 64;
#pragma unroll
        for (int nt = 0; nt < 8; nt++) {
            int gcol = wn + nt * 8 + (lane & 3) * 2;
            float b0 = bias[gcol], b1 = bias[gcol + 1];
#pragma unroll
            for (int hrow = 0; hrow < 2; hrow++) {
                int grow = brow + wm + (lane >> 2) + hrow * 8;
                if (grow < M) {
                    float o0 = fmaxf(acc[nt][hrow * 2 + 0] + b0, 0.f);
                    float o1 = fmaxf(acc[nt][hrow * 2 + 1] + b1, 0.f);
                    __half2 hp = __floats2half2_rn(o0, o1);
                    *(__half2*)(H + (size_t)grow * 256 + gcol) = hp;
                }
            }
        }
        buf ^= 1;
    }
}

// =============== persistent GEMM 2: C = act(H @ Wt2^T + b2) =================
// Single-pass fp16. 512 threads, warp tile 16x16, K=256. 2 CTAs/SM.
#define SROW2 528
#define G2_B (128 * SROW2)            // 67584
#define G2_AB (32 * SROW2)            // 16896 per buffer
#define G2_SMEM (G2_B + 2 * G2_AB)    // 101376

template <bool RELU, bool OUTHALF>
__global__ void __launch_bounds__(512, 2)
gemm2p(const __half* __restrict__ A, const __half* __restrict__ B,
       const float* __restrict__ bias, void* __restrict__ Cv, int M) {
    extern __shared__ char smem[];
    const uint32_t sb = smem_u32(smem);
    const uint32_t sB  = sb;
    const uint32_t sA0 = sb + G2_B;

    const int tid  = threadIdx.x;
    const int lane = tid & 31;
    const int wid  = tid >> 5;
    const int wm   = (wid & 1) * 16;
    const int wn   = (wid >> 1) * 16;

    // ---- load resident B: 128 rows x 512B ----
#pragma unroll
    for (int i = 0; i < 8; i++) {
        int id = tid + i * 512;
        int row = id >> 5, off = (id & 31) * 16;
        cp_async16(sB + (uint32_t)(row * SROW2 + off),
                   (const char*)(B + (size_t)row * 256) + off, 16);
    }

    int t = blockIdx.x;
    if (t < NT32) {
#pragma unroll
        for (int i = 0; i < 2; i++) {
            int id2 = tid + i * 512;
            int row = id2 >> 5, off = (id2 & 31) * 16;
            int grow = t * 32 + row;
            int asz = grow < M ? 16 : 0;
            cp_async16(sA0 + (uint32_t)(row * SROW2 + off),
                       (const char*)(A + (size_t)grow * 256) + off, asz);
        }
    }
    cp_commit();

    const uint32_t a_base = (uint32_t)((wm + (lane & 15)) * SROW2 + ((lane >> 4) << 4));
    const int bg = lane >> 3, br = lane & 7;
    const uint32_t b_base = (uint32_t)((wn + ((bg & 2) ? 8 : 0) + br) * SROW2 + ((bg & 1) << 4));

    int buf = 0;
    for (; t < NT32; t += GRIDP) {
        cp_wait0();
        __syncthreads();

        int tn = t + GRIDP;
        if (tn < NT32) {
            uint32_t base = sA0 + (buf ^ 1) * G2_AB;
#pragma unroll
            for (int i = 0; i < 2; i++) {
                int id2 = tid + i * 512;
                int row = id2 >> 5, off = (id2 & 31) * 16;
                int grow = tn * 32 + row;
                int asz = grow < M ? 16 : 0;
                cp_async16(base + (uint32_t)(row * SROW2 + off),
                           (const char*)(A + (size_t)grow * 256) + off, asz);
            }
        }
        cp_commit();

        const uint32_t cA = sA0 + buf * G2_AB;
        float acc[2][4];
#pragma unroll
        for (int j = 0; j < 2; j++)
#pragma unroll
            for (int k = 0; k < 4; k++) acc[j][k] = 0.f;

#pragma unroll
        for (int kk = 0; kk < 16; kk++) {
            const uint32_t kb = (uint32_t)(kk * 32);
            uint32_t af[4];
            ldsm_x4(af[0], af[1], af[2], af[3], cA + a_base + kb);
            uint32_t bf[2][2];
            {
                uint32_t r0, r1, r2, r3;
                ldsm_x4(r0, r1, r2, r3, sB + b_base + kb);
                bf[0][0] = r0; bf[0][1] = r1; bf[1][0] = r2; bf[1][1] = r3;
            }
#pragma unroll
            for (int nt = 0; nt < 2; nt++)
                mma16816(acc[nt], af, bf[nt]);
        }

        const int brow = t * 32;
#pragma unroll
        for (int nt = 0; nt < 2; nt++) {
            int gcol = wn + nt * 8 + (lane & 3) * 2;
            float b0 = bias[gcol], b1 = bias[gcol + 1];
#pragma unroll
            for (int hrow = 0; hrow < 2; hrow++) {
                int grow = brow + wm + (lane >> 2) + hrow * 8;
                if (grow < M) {
                    float o0 = acc[nt][hrow * 2 + 0] + b0;
                    float o1 = acc[nt][hrow * 2 + 1] + b1;
                    if (RELU) { o0 = fmaxf(o0, 0.f); o1 = fmaxf(o1, 0.f); }
                    if (OUTHALF) {
                        __half2 hp = __floats2half2_rn(o0, o1);
                        *(__half2*)((__half*)Cv + (size_t)grow * 128 + gcol) = hp;
                    } else {
                        *(float2*)((float*)Cv + (size_t)grow * 128 + gcol) = make_float2(o0, o1);
                    }
                }
            }
        }
        buf ^= 1;
    }
}

// ---------------- launch ----------------
extern "C" void kernel_launch(void* const* d_in, const int* in_sizes, int n_in,
                              void* d_out, int out_size) {
    const float* x     = (const float*)d_in[0];
    const int*   ei    = (const int*)d_in[1];
    const int*   ea    = (const int*)d_in[2];
    const float* ee1_0 = (const float*)d_in[3];
    const float* ee2_0 = (const float*)d_in[4];
    const float* W1_0  = (const float*)d_in[5];
    const float* b1_0  = (const float*)d_in[6];
    const float* W2_0  = (const float*)d_in[7];
    const float* b2_0  = (const float*)d_in[8];
    const float* ee1_1 = (const float*)d_in[9];
    const float* ee2_1 = (const float*)d_in[10];
    const float* W1_1  = (const float*)d_in[11];
    const float* b1_1  = (const float*)d_in[12];
    const float* W2_1  = (const float*)d_in[13];
    const float* b2_1  = (const float*)d_in[14];
    float* out = (float*)d_out;

    const int N = in_sizes[0] / DD;
    const int E = in_sizes[1] / 2;

    __half *x16, *A, *H, *Wt;
    int* cnt;
    uint32_t* payload;
    cudaGetSymbolAddress((void**)&x16, g_x16);
    cudaGetSymbolAddress((void**)&A, g_A);
    cudaGetSymbolAddress((void**)&H, g_H);
    cudaGetSymbolAddress((void**)&Wt, g_Wt);
    cudaGetSymbolAddress((void**)&cnt, g_cnt);
    cudaGetSymbolAddress((void**)&payload, g_payload);

    cudaFuncSetAttribute(gemm1p, cudaFuncAttributeMaxDynamicSharedMemorySize, G1_SMEM);
    cudaFuncSetAttribute(gemm2p<true, true>, cudaFuncAttributeMaxDynamicSharedMemorySize, G2_SMEM);
    cudaFuncSetAttribute(gemm2p<false, false>, cudaFuncAttributeMaxDynamicSharedMemorySize, G2_SMEM);

    const int ggrid = (N + 7) / 8;

    prep_kernel<<<512 + ZB + XCB, 256>>>(W1_0, W2_0, W1_1, W2_1, x, Wt, cnt, x16);
    fill_kernel<<<(E + 255) / 256, 256>>>(ei, ea, cnt, payload, E);

    // ============ layer 0 ============
    gather_kernel<<<ggrid, 256>>>(x16, cnt, payload, ee1_0, ee2_0, A, N);
    gemm1p<<<GRIDP, 512, G1_SMEM>>>(A, Wt + 0 * 32768, b1_0, H, N);
    gemm2p<true, true><<<GRIDP, 512, G2_SMEM>>>(H, Wt + 1 * 32768, b2_0, x16, N);

    // ============ layer 1 ============
    gather_kernel<<<ggrid, 256>>>(x16, cnt, payload, ee1_1, ee2_1, A, N);
    gemm1p<<<GRIDP, 512, G1_SMEM>>>(A, Wt + 2 * 32768, b1_1, H, N);
    gemm2p<false, false><<<GRIDP, 512, G2_SMEM>>>(H, Wt + 3 * 32768, b2_1, out, N);
}

// round 17
// speedup vs baseline: 2.9912x; 1.1541x over previous
#include <cuda_runtime.h>
#include <cuda_fp16.h>
#include <cstdint>

#define NN 50000
#define EE 800000
#define DD 128
#define BUCKET 64
#define GRIDF 148            // persistent fused grid: 1 CTA/SM
#define NT64 782             // ceil(50000/64)
#define ZB 196               // ceil(NN/256)
#define XCB 3125             // (NN*128)/(256*8)

// ---------------- scratch (static device globals) ----------------
__device__ __half g_x16[(size_t)NN * DD];        // fp16 node features (x, then y0)
__device__ __half g_A[(size_t)NN * DD];          // fp16 aggr
__device__ __half g_Wt[4][256 * 128];            // transposed fp16 weights
__device__ int g_cnt[NN];
__device__ uint32_t g_payload[(size_t)NN * BUCKET];

// ---------------- PTX helpers (base ISA only) ----------------
__device__ __forceinline__ uint32_t smem_u32(const void* p) {
    uint32_t a;
    asm("{ .reg .u64 t; cvta.to.shared.u64 t, %1; cvt.u32.u64 %0, t; }" : "=r"(a) : "l"(p));
    return a;
}
__device__ __forceinline__ void cp_async16(uint32_t dst, const void* src, int srcbytes) {
    asm volatile("cp.async.cg.shared.global [%0], [%1], 16, %2;"
                 :: "r"(dst), "l"(src), "r"(srcbytes) : "memory");
}
__device__ __forceinline__ void cp_commit() { asm volatile("cp.async.commit_group;" ::: "memory"); }
__device__ __forceinline__ void cp_wait0()  { asm volatile("cp.async.wait_group 0;" ::: "memory"); }

__device__ __forceinline__ void ldsm_x4(uint32_t& r0, uint32_t& r1, uint32_t& r2, uint32_t& r3,
                                        uint32_t addr) {
    asm volatile("ldmatrix.sync.aligned.m8n8.x4.shared.b16 {%0,%1,%2,%3}, [%4];"
                 : "=r"(r0), "=r"(r1), "=r"(r2), "=r"(r3) : "r"(addr));
}
__device__ __forceinline__ void mma16816(float* d, const uint32_t* a, const uint32_t* b) {
    asm volatile(
        "mma.sync.aligned.m16n8k16.row.col.f32.f16.f16.f32 "
        "{%0,%1,%2,%3}, {%4,%5,%6,%7}, {%8,%9}, {%0,%1,%2,%3};"
        : "+f"(d[0]), "+f"(d[1]), "+f"(d[2]), "+f"(d[3])
        : "r"(a[0]), "r"(a[1]), "r"(a[2]), "r"(a[3]), "r"(b[0]), "r"(b[1]));
}

// ------ prep: weight transposes (fp16) + zero cnt + x->fp16 ------
__global__ void __launch_bounds__(256)
prep_kernel(const float* __restrict__ W10, const float* __restrict__ W20,
            const float* __restrict__ W11, const float* __restrict__ W21,
            const float* __restrict__ x,
            __half* __restrict__ wt, int* __restrict__ cnt,
            __half* __restrict__ x16) {
    int b = blockIdx.x;
    int tid = threadIdx.x;
    if (b >= 512 + ZB) {                 // x -> fp16 convert
        long i = ((long)(b - 512 - ZB) * 256 + tid) * 8;
        float4 v0 = *(const float4*)(x + i);
        float4 v1 = *(const float4*)(x + i + 4);
        __half2 h0 = __floats2half2_rn(v0.x, v0.y);
        __half2 h1 = __floats2half2_rn(v0.z, v0.w);
        __half2 h2 = __floats2half2_rn(v1.x, v1.y);
        __half2 h3 = __floats2half2_rn(v1.z, v1.w);
        *(uint4*)(x16 + i) = make_uint4(*(uint32_t*)&h0, *(uint32_t*)&h1,
                                        *(uint32_t*)&h2, *(uint32_t*)&h3);
        return;
    }
    if (b >= 512) {                      // zero cnt
        int i = (b - 512) * 256 + tid;
        if (i < NN) cnt[i] = 0;
        return;
    }
    int which = b >> 7;
    int i = ((b & 127) << 8) + tid;
    const float* W;
    int K, N;
    if (which == 0)      { W = W10; K = 128; N = 256; }
    else if (which == 1) { W = W20; K = 256; N = 128; }
    else if (which == 2) { W = W11; K = 128; N = 256; }
    else                 { W = W21; K = 256; N = 128; }
    int k = i / N, n = i % N;
    wt[(size_t)which * 32768 + n * K + k] = __float2half_rn(W[i]);
}

// ---------------- bucket fill ----------------
__global__ void __launch_bounds__(256)
fill_kernel(const int* __restrict__ ei, const int* __restrict__ ea,
            int* __restrict__ cnt, uint32_t* __restrict__ payload, int E) {
    int e = blockIdx.x * 256 + threadIdx.x;
    if (e >= E) return;
    int src = ei[e];
    int dst = ei[E + e];
    int a0 = ea[2 * e];
    int a1 = ea[2 * e + 1];
    int pos = atomicAdd(&cnt[dst], 1);
    payload[((size_t)dst << 6) + pos] = (uint32_t)src | ((uint32_t)(a0 * 3 + a1) << 16);
}

// ---------------- gather (fp16 features) -> fp16 A ----------------
__global__ void __launch_bounds__(256)
gather_kernel(const __half* __restrict__ xh,
              const int* __restrict__ cnt, const uint32_t* __restrict__ payload,
              const float* __restrict__ ee1, const float* __restrict__ ee2,
              __half* __restrict__ A, int N) {
    __shared__ float combo[18 * 128];
    const int tid = threadIdx.x;
#pragma unroll
    for (int k = 0; k < 9; k++) {
        int idx = tid + k * 256;
        int c = idx >> 7, d = idx & 127;
        combo[idx] = ee1[(c / 3) * 128 + d] + ee2[(c % 3) * 128 + d];
    }
    __syncthreads();

    const int lane = tid & 31;
    const int n = blockIdx.x * 8 + (tid >> 5);
    if (n >= N) return;
    const int d4 = lane * 4;

    const uint32_t* pl = payload + ((size_t)n << 6);
    int deg = cnt[n];
    float4 acc = make_float4(0.f, 0.f, 0.f, 0.f);
    int i = 0;
    for (; i + 3 < deg; i += 4) {
        uint32_t p0 = pl[i], p1 = pl[i + 1], p2 = pl[i + 2], p3 = pl[i + 3];
        uint2 r0 = *(const uint2*)(xh + (size_t)(p0 & 0xFFFF) * 128 + d4);
        uint2 r1 = *(const uint2*)(xh + (size_t)(p1 & 0xFFFF) * 128 + d4);
        uint2 r2 = *(const uint2*)(xh + (size_t)(p2 & 0xFFFF) * 128 + d4);
        uint2 r3 = *(const uint2*)(xh + (size_t)(p3 & 0xFFFF) * 128 + d4);
        float4 c0 = *(const float4*)(combo + (p0 >> 16) * 128 + d4);
        float4 c1 = *(const float4*)(combo + (p1 >> 16) * 128 + d4);
        float4 c2 = *(const float4*)(combo + (p2 >> 16) * 128 + d4);
        float4 c3 = *(const float4*)(combo + (p3 >> 16) * 128 + d4);
        float2 a0 = __half22float2(*(__half2*)&r0.x), b0 = __half22float2(*(__half2*)&r0.y);
        float2 a1 = __half22float2(*(__half2*)&r1.x), b1 = __half22float2(*(__half2*)&r1.y);
        float2 a2 = __half22float2(*(__half2*)&r2.x), b2 = __half22float2(*(__half2*)&r2.y);
        float2 a3 = __half22float2(*(__half2*)&r3.x), b3 = __half22float2(*(__half2*)&r3.y);
        acc.x += (a0.x + c0.x) + (a1.x + c1.x) + (a2.x + c2.x) + (a3.x + c3.x);
        acc.y += (a0.y + c0.y) + (a1.y + c1.y) + (a2.y + c2.y) + (a3.y + c3.y);
        acc.z += (b0.x + c0.z) + (b1.x + c1.z) + (b2.x + c2.z) + (b3.x + c3.z);
        acc.w += (b0.y + c0.w) + (b1.y + c1.w) + (b2.y + c2.w) + (b3.y + c3.w);
    }
    for (; i < deg; i++) {
        uint32_t p0 = pl[i];
        uint2 r0 = *(const uint2*)(xh + (size_t)(p0 & 0xFFFF) * 128 + d4);
        float4 c0 = *(const float4*)(combo + (p0 >> 16) * 128 + d4);
        float2 a0 = __half22float2(*(__half2*)&r0.x), b0 = __half22float2(*(__half2*)&r0.y);
        acc.x += a0.x + c0.x;
        acc.y += a0.y + c0.y;
        acc.z += b0.x + c0.z;
        acc.w += b0.y + c0.w;
    }

    __half2 h01 = __floats2half2_rn(acc.x, acc.y);
    __half2 h23 = __floats2half2_rn(acc.z, acc.w);
    *(uint2*)(A + (size_t)n * 128 + d4) =
        make_uint2(*(uint32_t*)&h01, *(uint32_t*)&h23);
}

// =============== fused persistent MLP: C = act2(relu(A@W1^T+b1)@W2^T+b2) =====
// 512 threads = 16 warps. M-tile 64. W1 & W2 smem-resident, H tile staged in
// smem between the two GEMMs. 1 CTA/SM.
// GEMM1: warp tile 16x64 over N=256 (wm=(wid&3)*16, wn=(wid>>2)*64), K=128.
// GEMM2: warp tile 16x32 over N=128 (same wm,  wn2=(wid>>2)*32), K=256.
#define SROWB 272                     // 128 fp16 + pad
#define SROW2 528                     // 256 fp16 + pad
#define F_W1 (256 * SROWB)            // 69632
#define F_W2 (128 * SROW2)            // 67584
#define F_HT (64 * SROW2)             // 33792
#define F_AB (64 * SROWB)             // 17408 per buffer
#define OFF_W2 F_W1
#define OFF_HT (F_W1 + F_W2)
#define OFF_A  (F_W1 + F_W2 + F_HT)
#define FUS_SMEM (OFF_A + 2 * F_AB)   // 205824

template <bool OUTHALF>   // true: layer0 (relu2 + fp16 out), false: final fp32
__global__ void __launch_bounds__(512, 1)
fused_mlp(const __half* __restrict__ A, const __half* __restrict__ W1,
          const __half* __restrict__ W2,
          const float* __restrict__ b1, const float* __restrict__ b2,
          void* __restrict__ Cv, int M) {
    extern __shared__ char smem[];
    const uint32_t sb  = smem_u32(smem);
    const uint32_t sW1 = sb;
    const uint32_t sW2 = sb + OFF_W2;
    const uint32_t sHt = sb + OFF_HT;
    const uint32_t sA0 = sb + OFF_A;

    const int tid  = threadIdx.x;
    const int lane = tid & 31;
    const int wid  = tid >> 5;
    const int wm   = (wid & 3) * 16;
    const int wn   = (wid >> 2) * 64;   // gemm1 N offset
    const int wn2  = (wid >> 2) * 32;   // gemm2 N offset

    // ---- resident W1: 256 rows x 256B ----
#pragma unroll
    for (int i = 0; i < 8; i++) {
        int id = tid + i * 512;
        int row = id >> 4, off = (id & 15) * 16;
        cp_async16(sW1 + (uint32_t)(row * SROWB + off),
                   (const char*)(W1 + (size_t)row * 128) + off, 16);
    }
    // ---- resident W2: 128 rows x 512B ----
#pragma unroll
    for (int i = 0; i < 8; i++) {
        int id = tid + i * 512;
        int row = id >> 5, off = (id & 31) * 16;
        cp_async16(sW2 + (uint32_t)(row * SROW2 + off),
                   (const char*)(W2 + (size_t)row * 256) + off, 16);
    }

    // ---- issue first A tile: 64 rows x 256B ----
    int t = blockIdx.x;
    if (t < NT64) {
#pragma unroll
        for (int i = 0; i < 2; i++) {
            int id = tid + i * 512;
            int row = id >> 4, off = (id & 15) * 16;
            int grow = t * 64 + row;
            int asz = grow < M ? 16 : 0;
            cp_async16(sA0 + (uint32_t)(row * SROWB + off),
                       (const char*)(A + (size_t)grow * 128) + off, asz);
        }
    }
    cp_commit();

    // fragment addresses
    const uint32_t a_base = (uint32_t)((wm + (lane & 15)) * SROWB + ((lane >> 4) << 4));
    const int bg = lane >> 3, br = lane & 7;
    uint32_t b1_base[4];
#pragma unroll
    for (int np = 0; np < 4; np++)
        b1_base[np] = (uint32_t)((wn + np * 16 + ((bg & 2) ? 8 : 0) + br) * SROWB + ((bg & 1) << 4));
    const uint32_t h_base = (uint32_t)((wm + (lane & 15)) * SROW2 + ((lane >> 4) << 4));
    uint32_t b2_base[2];
#pragma unroll
    for (int np = 0; np < 2; np++)
        b2_base[np] = (uint32_t)((wn2 + np * 16 + ((bg & 2) ? 8 : 0) + br) * SROW2 + ((bg & 1) << 4));

    int buf = 0;
    for (; t < NT64; t += GRIDF) {
        cp_wait0();
        __syncthreads();   // A tile ready; also protects sHt reuse from prev iter

        int tn = t + GRIDF;
        if (tn < NT64) {
            uint32_t base = sA0 + (buf ^ 1) * F_AB;
#pragma unroll
            for (int i = 0; i < 2; i++) {
                int id = tid + i * 512;
                int row = id >> 4, off = (id & 15) * 16;
                int grow = tn * 64 + row;
                int asz = grow < M ? 16 : 0;
                cp_async16(base + (uint32_t)(row * SROWB + off),
                           (const char*)(A + (size_t)grow * 128) + off, asz);
            }
        }
        cp_commit();

        // ======== GEMM1: acc[8][4] = A(64x128) @ W1^T -> 64x256 ========
        const uint32_t cA = sA0 + buf * F_AB;
        float acc[8][4];
#pragma unroll
        for (int j = 0; j < 8; j++)
#pragma unroll
            for (int k = 0; k < 4; k++) acc[j][k] = 0.f;

#pragma unroll
        for (int kk = 0; kk < 8; kk++) {
            const uint32_t kb = (uint32_t)(kk * 32);
            uint32_t af[4];
            ldsm_x4(af[0], af[1], af[2], af[3], cA + a_base + kb);
            uint32_t bf[8][2];
#pragma unroll
            for (int np = 0; np < 4; np++) {
                uint32_t r0, r1, r2, r3;
                ldsm_x4(r0, r1, r2, r3, sW1 + b1_base[np] + kb);
                bf[np * 2][0] = r0; bf[np * 2][1] = r1;
                bf[np * 2 + 1][0] = r2; bf[np * 2 + 1][1] = r3;
            }
#pragma unroll
            for (int nt = 0; nt < 8; nt++)
                mma16816(acc[nt], af, bf[nt]);
        }

        // ---- epilogue1: relu(acc + b1) -> sHt (fp16, padded rows) ----
#pragma unroll
        for (int nt = 0; nt < 8; nt++) {
            int gcol = wn + nt * 8 + (lane & 3) * 2;
            float bb0 = b1[gcol], bb1 = b1[gcol + 1];
#pragma unroll
            for (int hrow = 0; hrow < 2; hrow++) {
                int rl = wm + (lane >> 2) + hrow * 8;
                float o0 = fmaxf(acc[nt][hrow * 2 + 0] + bb0, 0.f);
                float o1 = fmaxf(acc[nt][hrow * 2 + 1] + bb1, 0.f);
                __half2 hp = __floats2half2_rn(o0, o1);
                *(__half2*)(smem + OFF_HT + rl * SROW2 + gcol * 2) = hp;
            }
        }
        __syncthreads();   // H tile visible to all warps

        // ======== GEMM2: acc2[4][4] = H(64x256) @ W2^T -> 64x128 ========
        float acc2[4][4];
#pragma unroll
        for (int j = 0; j < 4; j++)
#pragma unroll
            for (int k = 0; k < 4; k++) acc2[j][k] = 0.f;

#pragma unroll
        for (int kk = 0; kk < 16; kk++) {
            const uint32_t kb = (uint32_t)(kk * 32);
            uint32_t af[4];
            ldsm_x4(af[0], af[1], af[2], af[3], sHt + h_base + kb);
            uint32_t bf[4][2];
#pragma unroll
            for (int np = 0; np < 2; np++) {
                uint32_t r0, r1, r2, r3;
                ldsm_x4(r0, r1, r2, r3, sW2 + b2_base[np] + kb);
                bf[np * 2][0] = r0; bf[np * 2][1] = r1;
                bf[np * 2 + 1][0] = r2; bf[np * 2 + 1][1] = r3;
            }
#pragma unroll
            for (int nt = 0; nt < 4; nt++)
                mma16816(acc2[nt], af, bf[nt]);
        }

        // ---- epilogue2: out = act2(acc2 + b2) ----
        const int brow = t * 64;
#pragma unroll
        for (int nt = 0; nt < 4; nt++) {
            int gcol = wn2 + nt * 8 + (lane & 3) * 2;
            float bb0 = b2[gcol], bb1 = b2[gcol + 1];
#pragma unroll
            for (int hrow = 0; hrow < 2; hrow++) {
                int grow = brow + wm + (lane >> 2) + hrow * 8;
                if (grow < M) {
                    float o0 = acc2[nt][hrow * 2 + 0] + bb0;
                    float o1 = acc2[nt][hrow * 2 + 1] + bb1;
                    if (OUTHALF) {
                        o0 = fmaxf(o0, 0.f);
                        o1 = fmaxf(o1, 0.f);
                        __half2 hp = __floats2half2_rn(o0, o1);
                        *(__half2*)((__half*)Cv + (size_t)grow * 128 + gcol) = hp;
                    } else {
                        *(float2*)((float*)Cv + (size_t)grow * 128 + gcol) = make_float2(o0, o1);
                    }
                }
            }
        }
        buf ^= 1;
    }
}

// ---------------- launch ----------------
extern "C" void kernel_launch(void* const* d_in, const int* in_sizes, int n_in,
                              void* d_out, int out_size) {
    const float* x     = (const float*)d_in[0];
    const int*   ei    = (const int*)d_in[1];
    const int*   ea    = (const int*)d_in[2];
    const float* ee1_0 = (const float*)d_in[3];
    const float* ee2_0 = (const float*)d_in[4];
    const float* W1_0  = (const float*)d_in[5];
    const float* b1_0  = (const float*)d_in[6];
    const float* W2_0  = (const float*)d_in[7];
    const float* b2_0  = (const float*)d_in[8];
    const float* ee1_1 = (const float*)d_in[9];
    const float* ee2_1 = (const float*)d_in[10];
    const float* W1_1  = (const float*)d_in[11];
    const float* b1_1  = (const float*)d_in[12];
    const float* W2_1  = (const float*)d_in[13];
    const float* b2_1  = (const float*)d_in[14];
    float* out = (float*)d_out;

    const int N = in_sizes[0] / DD;
    const int E = in_sizes[1] / 2;

    __half *x16, *A, *Wt;
    int* cnt;
    uint32_t* payload;
    cudaGetSymbolAddress((void**)&x16, g_x16);
    cudaGetSymbolAddress((void**)&A, g_A);
    cudaGetSymbolAddress((void**)&Wt, g_Wt);
    cudaGetSymbolAddress((void**)&cnt, g_cnt);
    cudaGetSymbolAddress((void**)&payload, g_payload);

    cudaFuncSetAttribute(fused_mlp<true>, cudaFuncAttributeMaxDynamicSharedMemorySize, FUS_SMEM);
    cudaFuncSetAttribute(fused_mlp<false>, cudaFuncAttributeMaxDynamicSharedMemorySize, FUS_SMEM);

    const int ggrid = (N + 7) / 8;

    prep_kernel<<<512 + ZB + XCB, 256>>>(W1_0, W2_0, W1_1, W2_1, x, Wt, cnt, x16);
    fill_kernel<<<(E + 255) / 256, 256>>>(ei, ea, cnt, payload, E);

    // ============ layer 0 ============
    gather_kernel<<<ggrid, 256>>>(x16, cnt, payload, ee1_0, ee2_0, A, N);
    fused_mlp<true><<<GRIDF, 512, FUS_SMEM>>>(A, Wt + 0 * 32768, Wt + 1 * 32768,
                                              b1_0, b2_0, x16, N);

    // ============ layer 1 ============
    gather_kernel<<<ggrid, 256>>>(x16, cnt, payload, ee1_1, ee2_1, A, N);
    fused_mlp<false><<<GRIDF, 512, FUS_SMEM>>>(A, Wt + 2 * 32768, Wt + 3 * 32768,
                                               b1_1, b2_1, out, N);
}